// round 2
// baseline (speedup 1.0000x reference)
#include <cuda_runtime.h>

// Problem constants (fixed shapes per reference)
#define BATCH 16
#define IC1   128
#define OCN   256
#define ZDIM  64
#define HIN   64
#define WIN   64
#define HO    32
#define WO    32
#define NPIX  (HO*WO)          // 1024
#define NGRP  8
#define CPG   (OCN/NGRP)       // 32
#define EPSV  1e-5f

#define NW1  (OCN*IC1*9)       // 294912
#define NW2  (OCN*OCN*9)       // 589824
#define NWSC (OCN*IC1)         // 32768

// Scratch (static device globals; no allocation allowed)
__device__ float g_w1 [(size_t)BATCH*NW1];
__device__ float g_w2 [(size_t)BATCH*NW2];
__device__ float g_wsc[(size_t)BATCH*NWSC];
__device__ float g_act1 [(size_t)BATCH*OCN*NPIX];
__device__ float g_conv2[(size_t)BATCH*OCN*NPIX];
__device__ float g_sc   [(size_t)BATCH*OCN*NPIX];
__device__ float g_stats1[BATCH*NGRP*2];
__device__ float g_stats2[BATCH*NGRP*2];

// ---------------------------------------------------------------------------
// Weight modulation: out[b, i] = base[i] + head_b[i] + dot(z[b,:], head_w[i,:])
// Each thread owns one weight row i, reads head_w row ONCE (64 floats), and
// produces results for all 16 batches (z lives in smem).
// ---------------------------------------------------------------------------
__global__ __launch_bounds__(256) void modw_kernel(
    const float* __restrict__ base, const float* __restrict__ hw,
    const float* __restrict__ hb,   const float* __restrict__ z,
    float* __restrict__ out, int nW)
{
    __shared__ float zs[BATCH*ZDIM];
    for (int i = threadIdx.x; i < BATCH*ZDIM; i += 256) zs[i] = z[i];
    __syncthreads();

    int i = blockIdx.x * 256 + threadIdx.x;
    if (i >= nW) return;

    float4 hwv[16];
    const float4* hwp = (const float4*)(hw + (size_t)i * ZDIM);
#pragma unroll
    for (int j = 0; j < 16; j++) hwv[j] = hwp[j];

    const float c = base[i] + hb[i];
#pragma unroll
    for (int b = 0; b < BATCH; b++) {
        const float* zb = zs + b * ZDIM;
        float acc = 0.f;
#pragma unroll
        for (int j = 0; j < 16; j++) {
            acc += hwv[j].x * zb[4*j+0];
            acc += hwv[j].y * zb[4*j+1];
            acc += hwv[j].z * zb[4*j+2];
            acc += hwv[j].w * zb[4*j+3];
        }
        out[(size_t)b * nW + i] = c + acc;
    }
}

// ---------------------------------------------------------------------------
// Tiled direct conv, per-batch weights.
// Block tile: 64 output channels x 8x8 output pixels. 256 threads.
// Thread tile: 4 oc x 4 px (register-blocked: 8 LDS per 16 FFMA).
// Grid: (16 spatial tiles, OC/64, B)
// ---------------------------------------------------------------------------
template<int KS, int STRIDE, int IC>
__global__ __launch_bounds__(256) void conv_kernel(
    const float* __restrict__ x, const float* __restrict__ w,
    float* __restrict__ out, int Hin, int Win)
{
    constexpr int PAD  = KS / 2;
    constexpr int ICC  = 8;
    constexpr int XT   = 7 * STRIDE + KS;        // input span for 8 outputs
    constexpr int XTW  = XT + 1;                 // pad to break conflicts
    constexpr int KK   = KS * KS;
    constexpr int WSTR = ICC * KK + 1;           // per-oc smem stride (odd)

    __shared__ float xs[ICC][XT][XTW];
    __shared__ float ws[64][WSTR];

    const int b   = blockIdx.z;
    const int oc0 = blockIdx.y * 64;
    const int tw0 = (blockIdx.x % (WO/8)) * 8;
    const int th0 = (blockIdx.x / (WO/8)) * 8;

    const float* xb = x + (size_t)b * IC * Hin * Win;
    const float* wb = w + ((size_t)b * OCN + oc0) * IC * KK;

    const int tx  = threadIdx.x;
    const int pr  = (tx & 15) >> 1;      // pixel row within 8x8
    const int pc0 = (tx & 1) * 4;        // pixel col base
    const int oci = (tx >> 4) * 4;       // local oc base

    float acc[4][4] = {};

    for (int ic0 = 0; ic0 < IC; ic0 += ICC) {
        // load input patch (zero-padded)
        for (int i = tx; i < ICC * XT * XT; i += 256) {
            int ic = i / (XT * XT);
            int r  = (i / XT) % XT;
            int c  = i % XT;
            int ih = th0 * STRIDE - PAD + r;
            int iw = tw0 * STRIDE - PAD + c;
            float v = 0.f;
            if (ih >= 0 && ih < Hin && iw >= 0 && iw < Win)
                v = xb[(size_t)(ic0 + ic) * Hin * Win + ih * Win + iw];
            xs[ic][r][c] = v;
        }
        // load weights (contiguous per oc slice)
        for (int i = tx; i < 64 * ICC * KK; i += 256) {
            int oc = i / (ICC * KK);
            int j  = i % (ICC * KK);
            ws[oc][j] = wb[(size_t)oc * IC * KK + ic0 * KK + j];
        }
        __syncthreads();

#pragma unroll
        for (int ic = 0; ic < ICC; ic++) {
#pragma unroll
            for (int kh = 0; kh < KS; kh++) {
#pragma unroll
                for (int kw = 0; kw < KS; kw++) {
                    float wv[4], xv[4];
#pragma unroll
                    for (int i = 0; i < 4; i++)
                        wv[i] = ws[oci + i][ic * KK + kh * KS + kw];
#pragma unroll
                    for (int j = 0; j < 4; j++)
                        xv[j] = xs[ic][pr * STRIDE + kh][(pc0 + j) * STRIDE + kw];
#pragma unroll
                    for (int i = 0; i < 4; i++)
#pragma unroll
                        for (int j = 0; j < 4; j++)
                            acc[i][j] += wv[i] * xv[j];
                }
            }
        }
        __syncthreads();
    }

#pragma unroll
    for (int i = 0; i < 4; i++) {
        size_t o = ((size_t)b * OCN + oc0 + oci + i) * NPIX + (th0 + pr) * WO + tw0 + pc0;
#pragma unroll
        for (int j = 0; j < 4; j++) out[o + j] = acc[i][j];
    }
}

// ---------------------------------------------------------------------------
// GroupNorm statistics: one block per (b, group); group data is contiguous
// (32 channels * 1024 px = 32768 floats). stats = {mean, rsqrt(var+eps)}.
// ---------------------------------------------------------------------------
__global__ __launch_bounds__(256) void gn_stats_kernel(
    const float* __restrict__ x, float* __restrict__ stats)
{
    const int bg = blockIdx.x;
    const float* p = x + (size_t)bg * (CPG * NPIX);
    float s = 0.f, ss = 0.f;
    for (int i = threadIdx.x; i < CPG * NPIX; i += 256) {
        float v = p[i];
        s += v; ss += v * v;
    }
    __shared__ float sh0[256], sh1[256];
    sh0[threadIdx.x] = s; sh1[threadIdx.x] = ss;
    __syncthreads();
    for (int o = 128; o > 0; o >>= 1) {
        if (threadIdx.x < o) {
            sh0[threadIdx.x] += sh0[threadIdx.x + o];
            sh1[threadIdx.x] += sh1[threadIdx.x + o];
        }
        __syncthreads();
    }
    if (threadIdx.x == 0) {
        const float n   = (float)(CPG * NPIX);
        float mu  = sh0[0] / n;
        float var = sh1[0] / n - mu * mu;
        stats[bg * 2 + 0] = mu;
        stats[bg * 2 + 1] = rsqrtf(var + EPSV);
    }
}

// GN1 apply + ReLU, in place
__global__ __launch_bounds__(256) void gn1_apply_kernel(
    float* __restrict__ x, const float* __restrict__ stats,
    const float* __restrict__ gamma, const float* __restrict__ beta)
{
    int idx = blockIdx.x * 256 + threadIdx.x;     // grid sized exactly
    int c   = (idx >> 10) & 255;                  // idx / 1024 mod 256
    int bg  = idx >> 15;                          // idx / 32768
    float mu = stats[bg * 2], ri = stats[bg * 2 + 1];
    float v  = (x[idx] - mu) * ri * gamma[c] + beta[c];
    x[idx] = fmaxf(v, 0.f);
}

// Final: out = relu(gn2(conv2) + shortcut)
__global__ __launch_bounds__(256) void final_kernel(
    const float* __restrict__ x, const float* __restrict__ sc,
    const float* __restrict__ stats,
    const float* __restrict__ gamma, const float* __restrict__ beta,
    float* __restrict__ out)
{
    int idx = blockIdx.x * 256 + threadIdx.x;
    int c   = (idx >> 10) & 255;
    int bg  = idx >> 15;
    float mu = stats[bg * 2], ri = stats[bg * 2 + 1];
    float v  = (x[idx] - mu) * ri * gamma[c] + beta[c] + sc[idx];
    out[idx] = fmaxf(v, 0.f);
}

// ---------------------------------------------------------------------------
extern "C" void kernel_launch(void* const* d_in, const int* in_sizes, int n_in,
                              void* d_out, int out_size)
{
    const float* x        = (const float*)d_in[0];
    const float* z        = (const float*)d_in[1];
    const float* base_w1  = (const float*)d_in[2];
    const float* head_w1  = (const float*)d_in[3];
    const float* head_b1  = (const float*)d_in[4];
    const float* gn_w1    = (const float*)d_in[5];
    const float* gn_b1    = (const float*)d_in[6];
    const float* base_w2  = (const float*)d_in[7];
    const float* head_w2  = (const float*)d_in[8];
    const float* head_b2  = (const float*)d_in[9];
    const float* gn_w2    = (const float*)d_in[10];
    const float* gn_b2    = (const float*)d_in[11];
    const float* base_wsc = (const float*)d_in[12];
    const float* head_wsc = (const float*)d_in[13];
    const float* head_bsc = (const float*)d_in[14];
    float* out = (float*)d_out;

    float *w1p, *w2p, *wscp, *a1p, *c2p, *scp, *st1p, *st2p;
    cudaGetSymbolAddress((void**)&w1p,  g_w1);
    cudaGetSymbolAddress((void**)&w2p,  g_w2);
    cudaGetSymbolAddress((void**)&wscp, g_wsc);
    cudaGetSymbolAddress((void**)&a1p,  g_act1);
    cudaGetSymbolAddress((void**)&c2p,  g_conv2);
    cudaGetSymbolAddress((void**)&scp,  g_sc);
    cudaGetSymbolAddress((void**)&st1p, g_stats1);
    cudaGetSymbolAddress((void**)&st2p, g_stats2);

    // 1. modulated weights
    modw_kernel<<<NW1  / 256, 256>>>(base_w1,  head_w1,  head_b1,  z, w1p,  NW1);
    modw_kernel<<<NW2  / 256, 256>>>(base_w2,  head_w2,  head_b2,  z, w2p,  NW2);
    modw_kernel<<<NWSC / 256, 256>>>(base_wsc, head_wsc, head_bsc, z, wscp, NWSC);

    // 2. conv1 (3x3, stride 2) and shortcut (1x1, stride 2)
    dim3 cgrid(16, OCN / 64, BATCH);
    conv_kernel<3, 2, IC1><<<cgrid, 256>>>(x, w1p,  a1p, HIN, WIN);
    conv_kernel<1, 2, IC1><<<cgrid, 256>>>(x, wscp, scp, HIN, WIN);

    // 3. GN1 + ReLU (in place on act1)
    gn_stats_kernel<<<BATCH * NGRP, 256>>>(a1p, st1p);
    gn1_apply_kernel<<<(BATCH * OCN * NPIX) / 256, 256>>>(a1p, st1p, gn_w1, gn_b1);

    // 4. conv2 (3x3, stride 1)
    conv_kernel<3, 1, OCN><<<cgrid, 256>>>(a1p, w2p, c2p, HO, WO);

    // 5. GN2 + residual + ReLU -> out
    gn_stats_kernel<<<BATCH * NGRP, 256>>>(c2p, st2p);
    final_kernel<<<(BATCH * OCN * NPIX) / 256, 256>>>(c2p, scp, st2p, gn_w2, gn_b2, out);
}

// round 4
// speedup vs baseline: 2.3582x; 2.3582x over previous
#include <cuda_runtime.h>
#include <cuda_bf16.h>
#include <cstdint>

// ---------------- problem dims ----------------
#define BATCH 16
#define IC1   128
#define OCN   256
#define ZDIM  64
#define HIN   64
#define WIN   64
#define HO    32
#define WO    32
#define NPIX  1024
#define NGRP  8
#define EPSV  1e-5f
#define PW1   66     // padded x: 66x66
#define PW2   34     // padded act1: 34x34

// ---------------- scratch (__device__ globals zero-init; halos stay 0) ----------------
__device__ __nv_bfloat16 g_xhi [(size_t)BATCH*PW1*PW1*IC1];
__device__ __nv_bfloat16 g_xlo [(size_t)BATCH*PW1*PW1*IC1];
__device__ __nv_bfloat16 g_ahi [(size_t)BATCH*PW2*PW2*OCN];
__device__ __nv_bfloat16 g_alo [(size_t)BATCH*PW2*PW2*OCN];
__device__ __nv_bfloat16 g_w1hi[(size_t)BATCH*9*OCN*IC1];
__device__ __nv_bfloat16 g_w1lo[(size_t)BATCH*9*OCN*IC1];
__device__ __nv_bfloat16 g_w2hi[(size_t)BATCH*9*OCN*OCN];
__device__ __nv_bfloat16 g_w2lo[(size_t)BATCH*9*OCN*OCN];
__device__ __nv_bfloat16 g_wshi[(size_t)BATCH*OCN*IC1];
__device__ __nv_bfloat16 g_wslo[(size_t)BATCH*OCN*IC1];
__device__ float g_c1out[(size_t)BATCH*NPIX*OCN];   // NHWC fp32
__device__ float g_c2out[(size_t)BATCH*NPIX*OCN];
__device__ float g_scout[(size_t)BATCH*NPIX*OCN];
__device__ float g_st1[BATCH*NGRP*2];
__device__ float g_st2[BATCH*NGRP*2];

// ---------------- helpers ----------------
__device__ __forceinline__ uint32_t smem_u32(const void* p) {
    uint32_t a;
    asm("{ .reg .u64 t; cvta.to.shared.u64 t, %1; cvt.u32.u64 %0, t; }" : "=r"(a) : "l"(p));
    return a;
}
#define SWZ(x) ((uint32_t)(x) ^ ((((uint32_t)(x)) >> 3) & 0x70u))

#define STS128V(addr, v) \
    asm volatile("st.shared.v4.b32 [%0], {%1,%2,%3,%4};" \
                 :: "r"(addr), "r"((v).x), "r"((v).y), "r"((v).z), "r"((v).w) : "memory")

#define LDSM4(r, addr) \
    asm volatile("ldmatrix.sync.aligned.m8n8.x4.shared.b16 {%0,%1,%2,%3}, [%4];" \
                 : "=r"((r)[0]), "=r"((r)[1]), "=r"((r)[2]), "=r"((r)[3]) : "r"(addr))

#define MMA16816(c, a, b0, b1) \
    asm volatile("mma.sync.aligned.m16n8k16.row.col.f32.bf16.bf16.f32 " \
                 "{%0,%1,%2,%3}, {%4,%5,%6,%7}, {%8,%9}, {%0,%1,%2,%3};" \
                 : "+f"((c)[0]), "+f"((c)[1]), "+f"((c)[2]), "+f"((c)[3]) \
                 : "r"((a)[0]), "r"((a)[1]), "r"((a)[2]), "r"((a)[3]), "r"(b0), "r"(b1))

// ---------------- prep: x NCHW fp32 -> padded NHWC bf16 hi/lo ----------------
__global__ __launch_bounds__(256) void prep_x_kernel(
    const float* __restrict__ x, __nv_bfloat16* __restrict__ xhi, __nv_bfloat16* __restrict__ xlo)
{
    __shared__ float s[32][33];
    const int wt = blockIdx.x & 1, ct = blockIdx.x >> 1;
    const int h = blockIdx.y, b = blockIdx.z;
    const int w0 = wt * 32, c0 = ct * 32;
    const int tx = threadIdx.x;
#pragma unroll
    for (int k = 0; k < 4; k++) {
        int idx = tx + k * 256;
        int ci = idx >> 5, wi = idx & 31;
        s[wi][ci] = x[(((size_t)b * IC1 + c0 + ci) * HIN + h) * WIN + w0 + wi];
    }
    __syncthreads();
#pragma unroll
    for (int k = 0; k < 4; k++) {
        int idx = tx + k * 256;
        int wi = idx >> 5, ci = idx & 31;
        float v = s[wi][ci];
        __nv_bfloat16 hi = __float2bfloat16(v);
        size_t o = (((size_t)b * PW1 + h + 1) * PW1 + (w0 + wi + 1)) * IC1 + c0 + ci;
        xhi[o] = hi;
        xlo[o] = __float2bfloat16(v - __bfloat162float(hi));
    }
}

// ---------------- weight modulation -> bf16 hi/lo, layout [b][tap][oc][ic] ----------------
template<int NTAP, int IC>
__global__ void modw_kernel(
    const float* __restrict__ base, const float* __restrict__ hw,
    const float* __restrict__ hb,   const float* __restrict__ z,
    __nv_bfloat16* __restrict__ whi, __nv_bfloat16* __restrict__ wlo)
{
    constexpr int ROWS = 8 * NTAP;
    constexpr int BT   = 32 * NTAP;
    __shared__ float hwS[ROWS * 65];
    __shared__ float zs[BATCH * ZDIM];
    __shared__ float cb[ROWS];
    const int oc  = blockIdx.x / (IC / 8);
    const int ic0 = (blockIdx.x % (IC / 8)) * 8;
    const int gi0 = (oc * IC + ic0) * NTAP;
    const int tx = threadIdx.x;
    for (int i = tx; i < ROWS * 64; i += BT)
        hwS[(i >> 6) * 65 + (i & 63)] = hw[(size_t)gi0 * 64 + i];
    for (int i = tx; i < BATCH * ZDIM; i += BT) zs[i] = z[i];
    for (int i = tx; i < ROWS; i += BT) cb[i] = base[gi0 + i] + hb[gi0 + i];
    __syncthreads();

    const int icl = tx & 7;
    const int tap = (tx >> 3) % NTAP;
    const int bq  = tx / (8 * NTAP);
    const int r   = icl * NTAP + tap;
    float acc[4] = {0.f, 0.f, 0.f, 0.f};
    for (int j = 0; j < 64; j++) {
        float h = hwS[r * 65 + j];
        acc[0] += h * zs[(bq * 4 + 0) * 64 + j];
        acc[1] += h * zs[(bq * 4 + 1) * 64 + j];
        acc[2] += h * zs[(bq * 4 + 2) * 64 + j];
        acc[3] += h * zs[(bq * 4 + 3) * 64 + j];
    }
#pragma unroll
    for (int bb = 0; bb < 4; bb++) {
        int b = bq * 4 + bb;
        float v = cb[r] + acc[bb];
        __nv_bfloat16 hi = __float2bfloat16(v);
        size_t o = (((size_t)b * NTAP + tap) * OCN + oc) * IC + ic0 + icl;
        whi[o] = hi;
        wlo[o] = __float2bfloat16(v - __bfloat162float(hi));
    }
}

// ---------------- conv via ldmatrix + mma.sync bf16 (split hi/lo, 3 passes) ----------
// Block: 256 thr = 8 warps (4 M x 2 N). Block tile M=128 px, N=128 oc, K-chunks 64.
// Grid: (8 px-tiles, 2 oc-halves, 16 batch)
template<int IC, int NTAP, int S, int PW>
__global__ __launch_bounds__(256, 2) void conv_mma_kernel(
    const __nv_bfloat16* __restrict__ ahi, const __nv_bfloat16* __restrict__ alo,
    const __nv_bfloat16* __restrict__ whi, const __nv_bfloat16* __restrict__ wlo,
    float* __restrict__ outp)
{
    extern __shared__ char smem_raw[];
    uint32_t sb = smem_u32(smem_raw);
    sb = (sb + 1023) & ~1023u;
    const uint32_t S_AH = sb;
    const uint32_t S_AL = sb + 16384;
    const uint32_t S_BH = sb + 32768;
    const uint32_t S_BL = sb + 49152;

    const int tx = threadIdx.x, lane = tx & 31, wid = tx >> 5;
    const int warpM = wid & 3, warpN = wid >> 2;
    const int mbase = warpM * 32, nbase = warpN * 64;

    const int b = blockIdx.z, oc0g = blockIdx.y * 128, p0 = blockIdx.x * 128;
    const size_t abase = (size_t)b * PW * PW * IC;

    // per-thread ldmatrix byte offsets (within tile, before swizzle)
    int rA[2], rB[4];
#pragma unroll
    for (int mt = 0; mt < 2; mt++)
        rA[mt] = (mbase + mt * 16 + (lane & 7) + ((lane >> 3) & 1) * 8) * 128
               + ((lane >> 4) & 1) * 16;
#pragma unroll
    for (int p = 0; p < 4; p++)
        rB[p] = (nbase + p * 16 + (lane & 7) + ((lane >> 4) & 1) * 8) * 128
              + ((lane >> 3) & 1) * 16;

    float acc[2][8][4] = {};

    constexpr int NCH = NTAP * IC / 64;
#pragma unroll 1
    for (int ch = 0; ch < NCH; ch++) {
        const int tap = ch / (IC / 64);
        const int ic0 = (ch % (IC / 64)) * 64;
        const int dh = (NTAP == 9) ? tap / 3 : 1;
        const int dw = (NTAP == 9) ? tap % 3 : 1;

        // ---- stage A tile [128 px][64 ic] hi+lo ----
#pragma unroll
        for (int pass = 0; pass < 4; pass++) {
            int idx = tx + pass * 256;
            int lr = idx >> 3, chunk = idx & 7;
            int px = p0 + lr;
            int oh = px >> 5, ow = px & 31;
            size_t src = abase + ((size_t)(oh * S + dh) * PW + (ow * S + dw)) * IC
                       + ic0 + chunk * 8;
            uint4 vh = *(const uint4*)(ahi + src);
            uint4 vl = *(const uint4*)(alo + src);
            uint32_t so = SWZ(lr * 128 + chunk * 16);
            STS128V(S_AH + so, vh);
            STS128V(S_AL + so, vl);
        }
        // ---- stage B tile [128 oc][64 ic] hi+lo ----
        const size_t wb = ((size_t)b * NTAP + tap) * OCN * IC + (size_t)oc0g * IC + ic0;
#pragma unroll
        for (int pass = 0; pass < 4; pass++) {
            int idx = tx + pass * 256;
            int row = idx >> 3, chunk = idx & 7;
            size_t src = wb + (size_t)row * IC + chunk * 8;
            uint4 vh = *(const uint4*)(whi + src);
            uint4 vl = *(const uint4*)(wlo + src);
            uint32_t so = SWZ(row * 128 + chunk * 16);
            STS128V(S_BH + so, vh);
            STS128V(S_BL + so, vl);
        }
        __syncthreads();

        // ---- warp MMA over K=64 (4 k16 steps), 3 split passes ----
#pragma unroll
        for (int ks = 0; ks < 4; ks++) {
            uint32_t ah[2][4], al[2][4], bf[4][4];
#pragma unroll
            for (int mt = 0; mt < 2; mt++) LDSM4(ah[mt], S_AH + SWZ(rA[mt] + ks * 32));
#pragma unroll
            for (int mt = 0; mt < 2; mt++) LDSM4(al[mt], S_AL + SWZ(rA[mt] + ks * 32));
#pragma unroll
            for (int p = 0; p < 4; p++)    LDSM4(bf[p], S_BH + SWZ(rB[p] + ks * 32));
#pragma unroll
            for (int mt = 0; mt < 2; mt++)
#pragma unroll
                for (int nt = 0; nt < 8; nt++)
                    MMA16816(acc[mt][nt], ah[mt], bf[nt >> 1][(nt & 1) * 2],
                             bf[nt >> 1][(nt & 1) * 2 + 1]);
#pragma unroll
            for (int mt = 0; mt < 2; mt++)
#pragma unroll
                for (int nt = 0; nt < 8; nt++)
                    MMA16816(acc[mt][nt], al[mt], bf[nt >> 1][(nt & 1) * 2],
                             bf[nt >> 1][(nt & 1) * 2 + 1]);
            // reload B-lo over B-hi registers
#pragma unroll
            for (int p = 0; p < 4; p++)    LDSM4(bf[p], S_BL + SWZ(rB[p] + ks * 32));
#pragma unroll
            for (int mt = 0; mt < 2; mt++)
#pragma unroll
                for (int nt = 0; nt < 8; nt++)
                    MMA16816(acc[mt][nt], ah[mt], bf[nt >> 1][(nt & 1) * 2],
                             bf[nt >> 1][(nt & 1) * 2 + 1]);
        }
        __syncthreads();
    }

    // ---- epilogue: NHWC fp32 ----
    float* ob = outp + (size_t)b * NPIX * OCN + oc0g;
#pragma unroll
    for (int mt = 0; mt < 2; mt++) {
        int px0 = p0 + mbase + mt * 16 + (lane >> 2);
#pragma unroll
        for (int nt = 0; nt < 8; nt++) {
            int oc = nbase + nt * 8 + (lane & 3) * 2;
            *(float2*)(ob + (size_t)px0 * OCN + oc) =
                make_float2(acc[mt][nt][0], acc[mt][nt][1]);
            *(float2*)(ob + (size_t)(px0 + 8) * OCN + oc) =
                make_float2(acc[mt][nt][2], acc[mt][nt][3]);
        }
    }
}

#define CONV_SMEM (65536 + 1024)

// ---------------- GroupNorm stats on NHWC fp32 ----------------
__global__ __launch_bounds__(256) void gn_stats_kernel(
    const float* __restrict__ x, float* __restrict__ stats)
{
    const int bg = blockIdx.x;
    const int b = bg >> 3, g = bg & 7;
    const float* base = x + (size_t)b * NPIX * OCN + g * 32;
    float s = 0.f, ss = 0.f;
    for (int i = threadIdx.x; i < NPIX * 32; i += 256) {
        float v = base[(size_t)(i >> 5) * OCN + (i & 31)];
        s += v; ss += v * v;
    }
    __shared__ float sh0[256], sh1[256];
    sh0[threadIdx.x] = s; sh1[threadIdx.x] = ss;
    __syncthreads();
    for (int o = 128; o > 0; o >>= 1) {
        if (threadIdx.x < o) { sh0[threadIdx.x] += sh0[threadIdx.x + o]; sh1[threadIdx.x] += sh1[threadIdx.x + o]; }
        __syncthreads();
    }
    if (threadIdx.x == 0) {
        const float n = 32768.f;
        float mu = sh0[0] / n;
        float var = sh1[0] / n - mu * mu;
        stats[bg * 2 + 0] = mu;
        stats[bg * 2 + 1] = rsqrtf(var + EPSV);
    }
}

// ---------------- GN1 + ReLU -> padded NHWC bf16 hi/lo ----------------
__global__ __launch_bounds__(256) void gn1_prep_kernel(
    const float* __restrict__ x, const float* __restrict__ stats,
    const float* __restrict__ gamma, const float* __restrict__ beta,
    __nv_bfloat16* __restrict__ ahi, __nv_bfloat16* __restrict__ alo)
{
    const size_t t = (size_t)blockIdx.x * 256 + threadIdx.x;
    const int c = (int)(t & 255);
    const int px = (int)((t >> 8) & 1023);
    const int b = (int)(t >> 18);
    const int bg = b * NGRP + (c >> 5);
    float mu = stats[bg * 2], ri = stats[bg * 2 + 1];
    float v = (x[t] - mu) * ri * gamma[c] + beta[c];
    v = fmaxf(v, 0.f);
    __nv_bfloat16 hi = __float2bfloat16(v);
    const int oh = px >> 5, ow = px & 31;
    size_t o = (((size_t)b * PW2 + oh + 1) * PW2 + ow + 1) * OCN + c;
    ahi[o] = hi;
    alo[o] = __float2bfloat16(v - __bfloat162float(hi));
}

// ---------------- final: relu(GN2(conv2) + shortcut), NHWC -> NCHW ----------------
__global__ __launch_bounds__(256) void final_kernel(
    const float* __restrict__ x, const float* __restrict__ sc,
    const float* __restrict__ stats,
    const float* __restrict__ gamma, const float* __restrict__ beta,
    float* __restrict__ out)
{
    __shared__ float s[32][33];
    const int pt = blockIdx.x, ct = blockIdx.y, b = blockIdx.z;
    const int px0 = pt * 32, c0 = ct * 32;
    const int tx = threadIdx.x;
    const int bg = b * NGRP + (c0 >> 5);
    const float mu = stats[bg * 2], ri = stats[bg * 2 + 1];
#pragma unroll
    for (int k = 0; k < 4; k++) {
        int idx = tx + k * 256;
        int pi = idx >> 5, ci = idx & 31;
        size_t o = ((size_t)b * NPIX + px0 + pi) * OCN + c0 + ci;
        float v = (x[o] - mu) * ri * gamma[c0 + ci] + beta[c0 + ci] + sc[o];
        s[pi][ci] = fmaxf(v, 0.f);
    }
    __syncthreads();
#pragma unroll
    for (int k = 0; k < 4; k++) {
        int idx = tx + k * 256;
        int cj = idx >> 5, wi = idx & 31;
        out[((size_t)b * OCN + c0 + cj) * NPIX + px0 + wi] = s[wi][cj];
    }
}

// ---------------- launch ----------------
extern "C" void kernel_launch(void* const* d_in, const int* in_sizes, int n_in,
                              void* d_out, int out_size)
{
    const float* x        = (const float*)d_in[0];
    const float* z        = (const float*)d_in[1];
    const float* base_w1  = (const float*)d_in[2];
    const float* head_w1  = (const float*)d_in[3];
    const float* head_b1  = (const float*)d_in[4];
    const float* gn_w1    = (const float*)d_in[5];
    const float* gn_b1    = (const float*)d_in[6];
    const float* base_w2  = (const float*)d_in[7];
    const float* head_w2  = (const float*)d_in[8];
    const float* head_b2  = (const float*)d_in[9];
    const float* gn_w2    = (const float*)d_in[10];
    const float* gn_b2    = (const float*)d_in[11];
    const float* base_wsc = (const float*)d_in[12];
    const float* head_wsc = (const float*)d_in[13];
    const float* head_bsc = (const float*)d_in[14];
    float* out = (float*)d_out;

    __nv_bfloat16 *xhi, *xlo, *ahi, *alo, *w1hi, *w1lo, *w2hi, *w2lo, *wshi, *wslo;
    float *c1p, *c2p, *scp, *st1, *st2;
    cudaGetSymbolAddress((void**)&xhi,  g_xhi);  cudaGetSymbolAddress((void**)&xlo,  g_xlo);
    cudaGetSymbolAddress((void**)&ahi,  g_ahi);  cudaGetSymbolAddress((void**)&alo,  g_alo);
    cudaGetSymbolAddress((void**)&w1hi, g_w1hi); cudaGetSymbolAddress((void**)&w1lo, g_w1lo);
    cudaGetSymbolAddress((void**)&w2hi, g_w2hi); cudaGetSymbolAddress((void**)&w2lo, g_w2lo);
    cudaGetSymbolAddress((void**)&wshi, g_wshi); cudaGetSymbolAddress((void**)&wslo, g_wslo);
    cudaGetSymbolAddress((void**)&c1p,  g_c1out); cudaGetSymbolAddress((void**)&c2p, g_c2out);
    cudaGetSymbolAddress((void**)&scp,  g_scout);
    cudaGetSymbolAddress((void**)&st1,  g_st1);  cudaGetSymbolAddress((void**)&st2,  g_st2);

    cudaFuncSetAttribute(conv_mma_kernel<IC1, 9, 2, PW1>, cudaFuncAttributeMaxDynamicSharedMemorySize, CONV_SMEM);
    cudaFuncSetAttribute(conv_mma_kernel<IC1, 1, 2, PW1>, cudaFuncAttributeMaxDynamicSharedMemorySize, CONV_SMEM);
    cudaFuncSetAttribute(conv_mma_kernel<OCN, 9, 1, PW2>, cudaFuncAttributeMaxDynamicSharedMemorySize, CONV_SMEM);

    // 1. prep x -> padded NHWC bf16 hi/lo
    prep_x_kernel<<<dim3(8, 64, 16), 256>>>(x, xhi, xlo);

    // 2. modulated weights (bf16 hi/lo, [b][tap][oc][ic])
    modw_kernel<9, IC1><<<OCN * (IC1 / 8), 288>>>(base_w1,  head_w1,  head_b1,  z, w1hi, w1lo);
    modw_kernel<9, OCN><<<OCN * (OCN / 8), 288>>>(base_w2,  head_w2,  head_b2,  z, w2hi, w2lo);
    modw_kernel<1, IC1><<<OCN * (IC1 / 8),  32>>>(base_wsc, head_wsc, head_bsc, z, wshi, wslo);

    // 3. conv1 (3x3 s2) + shortcut (1x1 s2) on tensor cores
    conv_mma_kernel<IC1, 9, 2, PW1><<<dim3(8, 2, 16), 256, CONV_SMEM>>>(xhi, xlo, w1hi, w1lo, c1p);
    conv_mma_kernel<IC1, 1, 2, PW1><<<dim3(8, 2, 16), 256, CONV_SMEM>>>(xhi, xlo, wshi, wslo, scp);

    // 4. GN1 + ReLU -> padded NHWC bf16 hi/lo
    gn_stats_kernel<<<BATCH * NGRP, 256>>>(c1p, st1);
    gn1_prep_kernel<<<(BATCH * NPIX * OCN) / 256, 256>>>(c1p, st1, gn_w1, gn_b1, ahi, alo);

    // 5. conv2 (3x3 s1)
    conv_mma_kernel<OCN, 9, 1, PW2><<<dim3(8, 2, 16), 256, CONV_SMEM>>>(ahi, alo, w2hi, w2lo, c2p);

    // 6. GN2 + residual + ReLU -> NCHW out
    gn_stats_kernel<<<BATCH * NGRP, 256>>>(c2p, st2);
    final_kernel<<<dim3(32, 8, 16), 256>>>(c2p, scp, st2, gn_w2, gn_b2, out);
}

// round 5
// speedup vs baseline: 2.4879x; 1.0550x over previous
#include <cuda_runtime.h>
#include <cuda_bf16.h>
#include <cstdint>

// ---------------- problem dims ----------------
#define BATCH 16
#define IC1   128
#define OCN   256
#define ZDIM  64
#define HIN   64
#define WIN   64
#define HO    32
#define WO    32
#define NPIX  1024
#define NGRP  8
#define EPSV  1e-5f
#define PW1   66     // padded x: 66x66
#define PW2   34     // padded act1: 34x34

// ---------------- scratch (__device__ globals zero-init; halos stay 0) ----------------
__device__ __nv_bfloat16 g_xhi [(size_t)BATCH*PW1*PW1*IC1];
__device__ __nv_bfloat16 g_xlo [(size_t)BATCH*PW1*PW1*IC1];
__device__ __nv_bfloat16 g_ahi [(size_t)BATCH*PW2*PW2*OCN];
__device__ __nv_bfloat16 g_alo [(size_t)BATCH*PW2*PW2*OCN];
__device__ __nv_bfloat16 g_w1hi[(size_t)BATCH*9*OCN*IC1];
__device__ __nv_bfloat16 g_w1lo[(size_t)BATCH*9*OCN*IC1];
__device__ __nv_bfloat16 g_w2hi[(size_t)BATCH*9*OCN*OCN];
__device__ __nv_bfloat16 g_w2lo[(size_t)BATCH*9*OCN*OCN];
__device__ __nv_bfloat16 g_wshi[(size_t)BATCH*OCN*IC1];
__device__ __nv_bfloat16 g_wslo[(size_t)BATCH*OCN*IC1];
__device__ float g_c1out[(size_t)BATCH*NPIX*OCN];   // NHWC fp32
__device__ float g_c2out[(size_t)BATCH*NPIX*OCN];
__device__ float g_scout[(size_t)BATCH*NPIX*OCN];
__device__ float g_st1[BATCH*NGRP*2];
__device__ float g_st2[BATCH*NGRP*2];

// ---------------- helpers ----------------
__device__ __forceinline__ uint32_t smem_u32(const void* p) {
    uint32_t a;
    asm("{ .reg .u64 t; cvta.to.shared.u64 t, %1; cvt.u32.u64 %0, t; }" : "=r"(a) : "l"(p));
    return a;
}
#define SWZ(x) ((uint32_t)(x) ^ ((((uint32_t)(x)) >> 3) & 0x70u))

#define CP16(dst, src) \
    asm volatile("cp.async.cg.shared.global [%0], [%1], 16;" :: "r"(dst), "l"(src))
#define CPCOMMIT() asm volatile("cp.async.commit_group;" ::: "memory")
#define CPWAIT1()  asm volatile("cp.async.wait_group 1;" ::: "memory")
#define CPWAIT0()  asm volatile("cp.async.wait_group 0;" ::: "memory")

#define LDSM4(r, addr) \
    asm volatile("ldmatrix.sync.aligned.m8n8.x4.shared.b16 {%0,%1,%2,%3}, [%4];" \
                 : "=r"((r)[0]), "=r"((r)[1]), "=r"((r)[2]), "=r"((r)[3]) : "r"(addr))

#define MMA16816(c, a, b0, b1) \
    asm volatile("mma.sync.aligned.m16n8k16.row.col.f32.bf16.bf16.f32 " \
                 "{%0,%1,%2,%3}, {%4,%5,%6,%7}, {%8,%9}, {%0,%1,%2,%3};" \
                 : "+f"((c)[0]), "+f"((c)[1]), "+f"((c)[2]), "+f"((c)[3]) \
                 : "r"((a)[0]), "r"((a)[1]), "r"((a)[2]), "r"((a)[3]), "r"(b0), "r"(b1))

// ---------------- prep: x NCHW fp32 -> padded NHWC bf16 hi/lo ----------------
__global__ __launch_bounds__(256) void prep_x_kernel(
    const float* __restrict__ x, __nv_bfloat16* __restrict__ xhi, __nv_bfloat16* __restrict__ xlo)
{
    __shared__ float s[32][33];
    const int wt = blockIdx.x & 1, ct = blockIdx.x >> 1;
    const int h = blockIdx.y, b = blockIdx.z;
    const int w0 = wt * 32, c0 = ct * 32;
    const int tx = threadIdx.x;
#pragma unroll
    for (int k = 0; k < 4; k++) {
        int idx = tx + k * 256;
        int ci = idx >> 5, wi = idx & 31;
        s[wi][ci] = x[(((size_t)b * IC1 + c0 + ci) * HIN + h) * WIN + w0 + wi];
    }
    __syncthreads();
#pragma unroll
    for (int k = 0; k < 4; k++) {
        int idx = tx + k * 256;
        int wi = idx >> 5, ci = idx & 31;
        float v = s[wi][ci];
        __nv_bfloat16 hi = __float2bfloat16(v);
        size_t o = (((size_t)b * PW1 + h + 1) * PW1 + (w0 + wi + 1)) * IC1 + c0 + ci;
        xhi[o] = hi;
        xlo[o] = __float2bfloat16(v - __bfloat162float(hi));
    }
}

// ---------------- weight modulation (3x3): bf16 hi/lo, [b][tap][oc][ic] ----------------
template<int NTAP, int IC>
__global__ void modw_kernel(
    const float* __restrict__ base, const float* __restrict__ hw,
    const float* __restrict__ hb,   const float* __restrict__ z,
    __nv_bfloat16* __restrict__ whi, __nv_bfloat16* __restrict__ wlo)
{
    constexpr int ROWS = 8 * NTAP;
    constexpr int BT   = 32 * NTAP;
    __shared__ float hwS[ROWS * 65];
    __shared__ float zs[BATCH * ZDIM];
    __shared__ float cb[ROWS];
    const int oc  = blockIdx.x / (IC / 8);
    const int ic0 = (blockIdx.x % (IC / 8)) * 8;
    const int gi0 = (oc * IC + ic0) * NTAP;
    const int tx = threadIdx.x;
    for (int i = tx; i < ROWS * 64; i += BT)
        hwS[(i >> 6) * 65 + (i & 63)] = hw[(size_t)gi0 * 64 + i];
    for (int i = tx; i < BATCH * ZDIM; i += BT) zs[i] = z[i];
    for (int i = tx; i < ROWS; i += BT) cb[i] = base[gi0 + i] + hb[gi0 + i];
    __syncthreads();

    const int icl = tx & 7;
    const int tap = (tx >> 3) % NTAP;
    const int bq  = tx / (8 * NTAP);
    const int r   = icl * NTAP + tap;
    float acc[4] = {0.f, 0.f, 0.f, 0.f};
    for (int j = 0; j < 64; j++) {
        float h = hwS[r * 65 + j];
        acc[0] += h * zs[(bq * 4 + 0) * 64 + j];
        acc[1] += h * zs[(bq * 4 + 1) * 64 + j];
        acc[2] += h * zs[(bq * 4 + 2) * 64 + j];
        acc[3] += h * zs[(bq * 4 + 3) * 64 + j];
    }
#pragma unroll
    for (int bb = 0; bb < 4; bb++) {
        int b = bq * 4 + bb;
        float v = cb[r] + acc[bb];
        __nv_bfloat16 hi = __float2bfloat16(v);
        size_t o = (((size_t)b * NTAP + tap) * OCN + oc) * IC + ic0 + icl;
        whi[o] = hi;
        wlo[o] = __float2bfloat16(v - __bfloat162float(hi));
    }
}

// ---------------- weight modulation (1x1 shortcut): one thread per row ----------------
__global__ __launch_bounds__(256) void modw1_kernel(
    const float* __restrict__ base, const float* __restrict__ hw,
    const float* __restrict__ hb,   const float* __restrict__ z,
    __nv_bfloat16* __restrict__ whi, __nv_bfloat16* __restrict__ wlo)
{
    __shared__ float zs[BATCH * ZDIM];
    for (int i = threadIdx.x; i < BATCH * ZDIM; i += 256) zs[i] = z[i];
    __syncthreads();

    const int i = blockIdx.x * 256 + threadIdx.x;   // row = oc*IC1 + ic
    float4 hwv[16];
    const float4* hwp = (const float4*)(hw + (size_t)i * ZDIM);
#pragma unroll
    for (int j = 0; j < 16; j++) hwv[j] = hwp[j];
    const float c = base[i] + hb[i];
#pragma unroll
    for (int b = 0; b < BATCH; b++) {
        const float* zb = zs + b * ZDIM;
        float acc = 0.f;
#pragma unroll
        for (int j = 0; j < 16; j++) {
            acc += hwv[j].x * zb[4*j+0];
            acc += hwv[j].y * zb[4*j+1];
            acc += hwv[j].z * zb[4*j+2];
            acc += hwv[j].w * zb[4*j+3];
        }
        float v = c + acc;
        __nv_bfloat16 hi = __float2bfloat16(v);
        size_t o = (size_t)b * (OCN * IC1) + i;     // matches [b][oc][ic]
        whi[o] = hi;
        wlo[o] = __float2bfloat16(v - __bfloat162float(hi));
    }
}

// ---------------- conv: ldmatrix + mma.sync bf16, split hi/lo, cp.async pipeline ----
// Block: 256 thr = 8 warps (4 M x 2 N). Block tile M=128 px, N=128 oc, K-chunks 64.
// Double-buffered smem (2 x 64KB). Grid: (8 px-tiles, 2 oc-halves, 16 batch)
template<int IC, int NTAP, int S, int PW>
__global__ __launch_bounds__(256, 1) void conv_mma_kernel(
    const __nv_bfloat16* __restrict__ ahi, const __nv_bfloat16* __restrict__ alo,
    const __nv_bfloat16* __restrict__ whi, const __nv_bfloat16* __restrict__ wlo,
    float* __restrict__ outp)
{
    extern __shared__ char smem_raw[];
    uint32_t sb = smem_u32(smem_raw);
    sb = (sb + 1023) & ~1023u;

    const int tx = threadIdx.x, lane = tx & 31, wid = tx >> 5;
    const int warpM = wid & 3, warpN = wid >> 2;
    const int mbase = warpM * 32, nbase = warpN * 64;

    const int b = blockIdx.z, oc0g = blockIdx.y * 128, p0 = blockIdx.x * 128;
    const size_t abase = (size_t)b * PW * PW * IC;
    constexpr int NCH = NTAP * IC / 64;

    // per-thread staging coords (fixed across chunks)
    const int lrA = tx >> 3, chkA = tx & 7;        // A row / 16B chunk (4 passes of 256)
    // per-thread ldmatrix byte offsets (within tile, before swizzle)
    int rA[2], rB[4];
#pragma unroll
    for (int mt = 0; mt < 2; mt++)
        rA[mt] = (mbase + mt * 16 + (lane & 7) + ((lane >> 3) & 1) * 8) * 128
               + ((lane >> 4) & 1) * 16;
#pragma unroll
    for (int p = 0; p < 4; p++)
        rB[p] = (nbase + p * 16 + (lane & 7) + ((lane >> 4) & 1) * 8) * 128
              + ((lane >> 3) & 1) * 16;

    float acc[2][8][4] = {};

    // ---- stage chunk ch into buffer (ch&1) ----
    auto stage = [&](int ch) {
        const uint32_t B0 = sb + (uint32_t)(ch & 1) * 65536u;
        const uint32_t SAH = B0, SAL = B0 + 16384, SBH = B0 + 32768, SBL = B0 + 49152;
        const int tap = ch / (IC / 64);
        const int ic0 = (ch % (IC / 64)) * 64;
        const int dh = (NTAP == 9) ? tap / 3 : 1;
        const int dw = (NTAP == 9) ? tap % 3 : 1;
#pragma unroll
        for (int pass = 0; pass < 4; pass++) {
            int lr = lrA + pass * 32;
            int px = p0 + lr;
            int oh = px >> 5, ow = px & 31;
            size_t src = abase + ((size_t)(oh * S + dh) * PW + (ow * S + dw)) * IC
                       + ic0 + chkA * 8;
            uint32_t so = SWZ(lr * 128 + chkA * 16);
            CP16(SAH + so, (const char*)(ahi + src));
            CP16(SAL + so, (const char*)(alo + src));
        }
        const size_t wb = ((size_t)b * NTAP + tap) * OCN * IC + (size_t)oc0g * IC + ic0;
#pragma unroll
        for (int pass = 0; pass < 4; pass++) {
            int row = lrA + pass * 32;
            size_t src = wb + (size_t)row * IC + chkA * 8;
            uint32_t so = SWZ(row * 128 + chkA * 16);
            CP16(SBH + so, (const char*)(whi + src));
            CP16(SBL + so, (const char*)(wlo + src));
        }
        CPCOMMIT();
    };

    stage(0);
#pragma unroll 1
    for (int ch = 0; ch < NCH; ch++) {
        if (ch + 1 < NCH) { stage(ch + 1); CPWAIT1(); }
        else              { CPWAIT0(); }
        __syncthreads();

        const uint32_t B0 = sb + (uint32_t)(ch & 1) * 65536u;
        const uint32_t SAH = B0, SAL = B0 + 16384, SBH = B0 + 32768, SBL = B0 + 49152;
#pragma unroll
        for (int ks = 0; ks < 4; ks++) {
            uint32_t ah[2][4], al[2][4], bf[4][4];
#pragma unroll
            for (int mt = 0; mt < 2; mt++) LDSM4(ah[mt], SAH + SWZ(rA[mt] + ks * 32));
#pragma unroll
            for (int mt = 0; mt < 2; mt++) LDSM4(al[mt], SAL + SWZ(rA[mt] + ks * 32));
#pragma unroll
            for (int p = 0; p < 4; p++)    LDSM4(bf[p], SBH + SWZ(rB[p] + ks * 32));
#pragma unroll
            for (int mt = 0; mt < 2; mt++)
#pragma unroll
                for (int nt = 0; nt < 8; nt++)
                    MMA16816(acc[mt][nt], ah[mt], bf[nt >> 1][(nt & 1) * 2],
                             bf[nt >> 1][(nt & 1) * 2 + 1]);
#pragma unroll
            for (int mt = 0; mt < 2; mt++)
#pragma unroll
                for (int nt = 0; nt < 8; nt++)
                    MMA16816(acc[mt][nt], al[mt], bf[nt >> 1][(nt & 1) * 2],
                             bf[nt >> 1][(nt & 1) * 2 + 1]);
            // reload B-lo over B-hi registers
#pragma unroll
            for (int p = 0; p < 4; p++)    LDSM4(bf[p], SBL + SWZ(rB[p] + ks * 32));
#pragma unroll
            for (int mt = 0; mt < 2; mt++)
#pragma unroll
                for (int nt = 0; nt < 8; nt++)
                    MMA16816(acc[mt][nt], ah[mt], bf[nt >> 1][(nt & 1) * 2],
                             bf[nt >> 1][(nt & 1) * 2 + 1]);
        }
        __syncthreads();
    }

    // ---- epilogue: NHWC fp32 ----
    float* ob = outp + (size_t)b * NPIX * OCN + oc0g;
#pragma unroll
    for (int mt = 0; mt < 2; mt++) {
        int px0 = p0 + mbase + mt * 16 + (lane >> 2);
#pragma unroll
        for (int nt = 0; nt < 8; nt++) {
            int oc = nbase + nt * 8 + (lane & 3) * 2;
            *(float2*)(ob + (size_t)px0 * OCN + oc) =
                make_float2(acc[mt][nt][0], acc[mt][nt][1]);
            *(float2*)(ob + (size_t)(px0 + 8) * OCN + oc) =
                make_float2(acc[mt][nt][2], acc[mt][nt][3]);
        }
    }
}

#define CONV_SMEM (2 * 65536 + 1024)

// ---------------- GroupNorm stats on NHWC fp32 ----------------
__global__ __launch_bounds__(256) void gn_stats_kernel(
    const float* __restrict__ x, float* __restrict__ stats)
{
    const int bg = blockIdx.x;
    const int b = bg >> 3, g = bg & 7;
    const float* base = x + (size_t)b * NPIX * OCN + g * 32;
    float s = 0.f, ss = 0.f;
    for (int i = threadIdx.x; i < NPIX * 32; i += 256) {
        float v = base[(size_t)(i >> 5) * OCN + (i & 31)];
        s += v; ss += v * v;
    }
    __shared__ float sh0[256], sh1[256];
    sh0[threadIdx.x] = s; sh1[threadIdx.x] = ss;
    __syncthreads();
    for (int o = 128; o > 0; o >>= 1) {
        if (threadIdx.x < o) { sh0[threadIdx.x] += sh0[threadIdx.x + o]; sh1[threadIdx.x] += sh1[threadIdx.x + o]; }
        __syncthreads();
    }
    if (threadIdx.x == 0) {
        const float n = 32768.f;
        float mu = sh0[0] / n;
        float var = sh1[0] / n - mu * mu;
        stats[bg * 2 + 0] = mu;
        stats[bg * 2 + 1] = rsqrtf(var + EPSV);
    }
}

// ---------------- GN1 + ReLU -> padded NHWC bf16 hi/lo ----------------
__global__ __launch_bounds__(256) void gn1_prep_kernel(
    const float* __restrict__ x, const float* __restrict__ stats,
    const float* __restrict__ gamma, const float* __restrict__ beta,
    __nv_bfloat16* __restrict__ ahi, __nv_bfloat16* __restrict__ alo)
{
    const size_t t = (size_t)blockIdx.x * 256 + threadIdx.x;
    const int c = (int)(t & 255);
    const int px = (int)((t >> 8) & 1023);
    const int b = (int)(t >> 18);
    const int bg = b * NGRP + (c >> 5);
    float mu = stats[bg * 2], ri = stats[bg * 2 + 1];
    float v = (x[t] - mu) * ri * gamma[c] + beta[c];
    v = fmaxf(v, 0.f);
    __nv_bfloat16 hi = __float2bfloat16(v);
    const int oh = px >> 5, ow = px & 31;
    size_t o = (((size_t)b * PW2 + oh + 1) * PW2 + ow + 1) * OCN + c;
    ahi[o] = hi;
    alo[o] = __float2bfloat16(v - __bfloat162float(hi));
}

// ---------------- final: relu(GN2(conv2) + shortcut), NHWC -> NCHW ----------------
__global__ __launch_bounds__(256) void final_kernel(
    const float* __restrict__ x, const float* __restrict__ sc,
    const float* __restrict__ stats,
    const float* __restrict__ gamma, const float* __restrict__ beta,
    float* __restrict__ out)
{
    __shared__ float s[32][33];
    const int pt = blockIdx.x, ct = blockIdx.y, b = blockIdx.z;
    const int px0 = pt * 32, c0 = ct * 32;
    const int tx = threadIdx.x;
    const int bg = b * NGRP + (c0 >> 5);
    const float mu = stats[bg * 2], ri = stats[bg * 2 + 1];
#pragma unroll
    for (int k = 0; k < 4; k++) {
        int idx = tx + k * 256;
        int pi = idx >> 5, ci = idx & 31;
        size_t o = ((size_t)b * NPIX + px0 + pi) * OCN + c0 + ci;
        float v = (x[o] - mu) * ri * gamma[c0 + ci] + beta[c0 + ci] + sc[o];
        s[pi][ci] = fmaxf(v, 0.f);
    }
    __syncthreads();
#pragma unroll
    for (int k = 0; k < 4; k++) {
        int idx = tx + k * 256;
        int cj = idx >> 5, wi = idx & 31;
        out[((size_t)b * OCN + c0 + cj) * NPIX + px0 + wi] = s[wi][cj];
    }
}

// ---------------- launch ----------------
extern "C" void kernel_launch(void* const* d_in, const int* in_sizes, int n_in,
                              void* d_out, int out_size)
{
    const float* x        = (const float*)d_in[0];
    const float* z        = (const float*)d_in[1];
    const float* base_w1  = (const float*)d_in[2];
    const float* head_w1  = (const float*)d_in[3];
    const float* head_b1  = (const float*)d_in[4];
    const float* gn_w1    = (const float*)d_in[5];
    const float* gn_b1    = (const float*)d_in[6];
    const float* base_w2  = (const float*)d_in[7];
    const float* head_w2  = (const float*)d_in[8];
    const float* head_b2  = (const float*)d_in[9];
    const float* gn_w2    = (const float*)d_in[10];
    const float* gn_b2    = (const float*)d_in[11];
    const float* base_wsc = (const float*)d_in[12];
    const float* head_wsc = (const float*)d_in[13];
    const float* head_bsc = (const float*)d_in[14];
    float* out = (float*)d_out;

    __nv_bfloat16 *xhi, *xlo, *ahi, *alo, *w1hi, *w1lo, *w2hi, *w2lo, *wshi, *wslo;
    float *c1p, *c2p, *scp, *st1, *st2;
    cudaGetSymbolAddress((void**)&xhi,  g_xhi);  cudaGetSymbolAddress((void**)&xlo,  g_xlo);
    cudaGetSymbolAddress((void**)&ahi,  g_ahi);  cudaGetSymbolAddress((void**)&alo,  g_alo);
    cudaGetSymbolAddress((void**)&w1hi, g_w1hi); cudaGetSymbolAddress((void**)&w1lo, g_w1lo);
    cudaGetSymbolAddress((void**)&w2hi, g_w2hi); cudaGetSymbolAddress((void**)&w2lo, g_w2lo);
    cudaGetSymbolAddress((void**)&wshi, g_wshi); cudaGetSymbolAddress((void**)&wslo, g_wslo);
    cudaGetSymbolAddress((void**)&c1p,  g_c1out); cudaGetSymbolAddress((void**)&c2p, g_c2out);
    cudaGetSymbolAddress((void**)&scp,  g_scout);
    cudaGetSymbolAddress((void**)&st1,  g_st1);  cudaGetSymbolAddress((void**)&st2,  g_st2);

    cudaFuncSetAttribute(conv_mma_kernel<IC1, 9, 2, PW1>, cudaFuncAttributeMaxDynamicSharedMemorySize, CONV_SMEM);
    cudaFuncSetAttribute(conv_mma_kernel<IC1, 1, 2, PW1>, cudaFuncAttributeMaxDynamicSharedMemorySize, CONV_SMEM);
    cudaFuncSetAttribute(conv_mma_kernel<OCN, 9, 1, PW2>, cudaFuncAttributeMaxDynamicSharedMemorySize, CONV_SMEM);

    // 1. prep x -> padded NHWC bf16 hi/lo
    prep_x_kernel<<<dim3(8, 64, 16), 256>>>(x, xhi, xlo);

    // 2. modulated weights (bf16 hi/lo)
    modw_kernel<9, IC1><<<OCN * (IC1 / 8), 288>>>(base_w1,  head_w1,  head_b1,  z, w1hi, w1lo);
    modw_kernel<9, OCN><<<OCN * (OCN / 8), 288>>>(base_w2,  head_w2,  head_b2,  z, w2hi, w2lo);
    modw1_kernel<<<(OCN * IC1) / 256, 256>>>(base_wsc, head_wsc, head_bsc, z, wshi, wslo);

    // 3. conv1 (3x3 s2) + shortcut (1x1 s2) on tensor cores
    conv_mma_kernel<IC1, 9, 2, PW1><<<dim3(8, 2, 16), 256, CONV_SMEM>>>(xhi, xlo, w1hi, w1lo, c1p);
    conv_mma_kernel<IC1, 1, 2, PW1><<<dim3(8, 2, 16), 256, CONV_SMEM>>>(xhi, xlo, wshi, wslo, scp);

    // 4. GN1 + ReLU -> padded NHWC bf16 hi/lo
    gn_stats_kernel<<<BATCH * NGRP, 256>>>(c1p, st1);
    gn1_prep_kernel<<<(BATCH * NPIX * OCN) / 256, 256>>>(c1p, st1, gn_w1, gn_b1, ahi, alo);

    // 5. conv2 (3x3 s1)
    conv_mma_kernel<OCN, 9, 1, PW2><<<dim3(8, 2, 16), 256, CONV_SMEM>>>(ahi, alo, w2hi, w2lo, c2p);

    // 6. GN2 + residual + ReLU -> NCHW out
    gn_stats_kernel<<<BATCH * NGRP, 256>>>(c2p, st2);
    final_kernel<<<dim3(32, 8, 16), 256>>>(c2p, scp, st2, gn_w2, gn_b2, out);
}

// round 6
// speedup vs baseline: 2.7997x; 1.1254x over previous
#include <cuda_runtime.h>
#include <cuda_bf16.h>
#include <cstdint>

// ---------------- problem dims ----------------
#define BATCH 16
#define IC1   128
#define OCN   256
#define ZDIM  64
#define HIN   64
#define WIN   64
#define HO    32
#define WO    32
#define NPIX  1024
#define NGRP  8
#define EPSV  1e-5f
#define PW1   66     // padded x: 66x66
#define PW2   34     // padded act1: 34x34

// ---------------- scratch (__device__ globals zero-init; halos stay 0) ----------------
__device__ __nv_bfloat16 g_xhi [(size_t)BATCH*PW1*PW1*IC1];
__device__ __nv_bfloat16 g_xlo [(size_t)BATCH*PW1*PW1*IC1];
__device__ __nv_bfloat16 g_ahi [(size_t)BATCH*PW2*PW2*OCN];
__device__ __nv_bfloat16 g_alo [(size_t)BATCH*PW2*PW2*OCN];
__device__ __nv_bfloat16 g_w1hi[(size_t)BATCH*9*OCN*IC1];
__device__ __nv_bfloat16 g_w1lo[(size_t)BATCH*9*OCN*IC1];
__device__ __nv_bfloat16 g_w2hi[(size_t)BATCH*9*OCN*OCN];
__device__ __nv_bfloat16 g_w2lo[(size_t)BATCH*9*OCN*OCN];
__device__ __nv_bfloat16 g_wshi[(size_t)BATCH*OCN*IC1];
__device__ __nv_bfloat16 g_wslo[(size_t)BATCH*OCN*IC1];
__device__ float g_c1out[(size_t)BATCH*NPIX*OCN];   // NHWC fp32
__device__ float g_c2out[(size_t)BATCH*NPIX*OCN];
__device__ float g_scout[(size_t)BATCH*NPIX*OCN];
__device__ float g_st1[BATCH*NGRP*2];
__device__ float g_st2[BATCH*NGRP*2];

// ---------------- helpers ----------------
__device__ __forceinline__ uint32_t smem_u32(const void* p) {
    uint32_t a;
    asm("{ .reg .u64 t; cvta.to.shared.u64 t, %1; cvt.u32.u64 %0, t; }" : "=r"(a) : "l"(p));
    return a;
}
#define SWZ(x) ((uint32_t)(x) ^ ((((uint32_t)(x)) >> 3) & 0x70u))

#define CP16(dst, src) \
    asm volatile("cp.async.cg.shared.global [%0], [%1], 16;" :: "r"(dst), "l"(src))
#define CPCOMMIT() asm volatile("cp.async.commit_group;" ::: "memory")
#define CPWAIT0()  asm volatile("cp.async.wait_group 0;" ::: "memory")

#define LDSM4(r, addr) \
    asm volatile("ldmatrix.sync.aligned.m8n8.x4.shared.b16 {%0,%1,%2,%3}, [%4];" \
                 : "=r"((r)[0]), "=r"((r)[1]), "=r"((r)[2]), "=r"((r)[3]) : "r"(addr))

#define MMA16816(c, a, b0, b1) \
    asm volatile("mma.sync.aligned.m16n8k16.row.col.f32.bf16.bf16.f32 " \
                 "{%0,%1,%2,%3}, {%4,%5,%6,%7}, {%8,%9}, {%0,%1,%2,%3};" \
                 : "+f"((c)[0]), "+f"((c)[1]), "+f"((c)[2]), "+f"((c)[3]) \
                 : "r"((a)[0]), "r"((a)[1]), "r"((a)[2]), "r"((a)[3]), "r"(b0), "r"(b1))

__device__ __forceinline__ uint32_t pk_bf2(__nv_bfloat16 a, __nv_bfloat16 b) {
    __nv_bfloat162 t = __halves2bfloat162(a, b);
    return *(uint32_t*)&t;
}

// ---------------- prep: x NCHW fp32 -> padded NHWC bf16 hi/lo ----------------
__global__ __launch_bounds__(256) void prep_x_kernel(
    const float* __restrict__ x, __nv_bfloat16* __restrict__ xhi, __nv_bfloat16* __restrict__ xlo)
{
    __shared__ float s[32][33];
    const int wt = blockIdx.x & 1, ct = blockIdx.x >> 1;
    const int h = blockIdx.y, b = blockIdx.z;
    const int w0 = wt * 32, c0 = ct * 32;
    const int tx = threadIdx.x;
#pragma unroll
    for (int k = 0; k < 4; k++) {
        int idx = tx + k * 256;
        int ci = idx >> 5, wi = idx & 31;
        s[wi][ci] = x[(((size_t)b * IC1 + c0 + ci) * HIN + h) * WIN + w0 + wi];
    }
    __syncthreads();
    // each thread: 4 consecutive channels -> 8B vector stores
    const int wi = tx >> 3, cg = tx & 7;
    __nv_bfloat16 hi[4], lo[4];
#pragma unroll
    for (int j = 0; j < 4; j++) {
        float v = s[wi][cg * 4 + j];
        hi[j] = __float2bfloat16(v);
        lo[j] = __float2bfloat16(v - __bfloat162float(hi[j]));
    }
    size_t o = (((size_t)b * PW1 + h + 1) * PW1 + (w0 + wi + 1)) * IC1 + c0 + cg * 4;
    *(uint2*)(xhi + o) = make_uint2(pk_bf2(hi[0], hi[1]), pk_bf2(hi[2], hi[3]));
    *(uint2*)(xlo + o) = make_uint2(pk_bf2(lo[0], lo[1]), pk_bf2(lo[2], lo[3]));
}

// ---------------- weight modulation (3x3): bf16 hi/lo, [b][tap][oc][ic] ----------------
template<int NTAP, int IC>
__global__ void modw_kernel(
    const float* __restrict__ base, const float* __restrict__ hw,
    const float* __restrict__ hb,   const float* __restrict__ z,
    __nv_bfloat16* __restrict__ whi, __nv_bfloat16* __restrict__ wlo)
{
    constexpr int ROWS = 8 * NTAP;
    constexpr int BT   = 32 * NTAP;
    __shared__ float hwS[ROWS * 65];
    __shared__ float zs[BATCH * ZDIM];
    __shared__ float cb[ROWS];
    const int oc  = blockIdx.x / (IC / 8);
    const int ic0 = (blockIdx.x % (IC / 8)) * 8;
    const int gi0 = (oc * IC + ic0) * NTAP;
    const int tx = threadIdx.x;
    for (int i = tx; i < ROWS * 64; i += BT)
        hwS[(i >> 6) * 65 + (i & 63)] = hw[(size_t)gi0 * 64 + i];
    for (int i = tx; i < BATCH * ZDIM; i += BT) zs[i] = z[i];
    for (int i = tx; i < ROWS; i += BT) cb[i] = base[gi0 + i] + hb[gi0 + i];
    __syncthreads();

    const int icl = tx & 7;
    const int tap = (tx >> 3) % NTAP;
    const int bq  = tx / (8 * NTAP);
    const int r   = icl * NTAP + tap;
    float acc[4] = {0.f, 0.f, 0.f, 0.f};
    for (int j = 0; j < 64; j++) {
        float h = hwS[r * 65 + j];
        acc[0] += h * zs[(bq * 4 + 0) * 64 + j];
        acc[1] += h * zs[(bq * 4 + 1) * 64 + j];
        acc[2] += h * zs[(bq * 4 + 2) * 64 + j];
        acc[3] += h * zs[(bq * 4 + 3) * 64 + j];
    }
#pragma unroll
    for (int bb = 0; bb < 4; bb++) {
        int b = bq * 4 + bb;
        float v = cb[r] + acc[bb];
        __nv_bfloat16 hi = __float2bfloat16(v);
        size_t o = (((size_t)b * NTAP + tap) * OCN + oc) * IC + ic0 + icl;
        whi[o] = hi;
        wlo[o] = __float2bfloat16(v - __bfloat162float(hi));
    }
}

// ---------------- weight modulation (1x1 shortcut): one thread per row ----------------
__global__ __launch_bounds__(256) void modw1_kernel(
    const float* __restrict__ base, const float* __restrict__ hw,
    const float* __restrict__ hb,   const float* __restrict__ z,
    __nv_bfloat16* __restrict__ whi, __nv_bfloat16* __restrict__ wlo)
{
    __shared__ float zs[BATCH * ZDIM];
    for (int i = threadIdx.x; i < BATCH * ZDIM; i += 256) zs[i] = z[i];
    __syncthreads();

    const int i = blockIdx.x * 256 + threadIdx.x;
    float4 hwv[16];
    const float4* hwp = (const float4*)(hw + (size_t)i * ZDIM);
#pragma unroll
    for (int j = 0; j < 16; j++) hwv[j] = hwp[j];
    const float c = base[i] + hb[i];
#pragma unroll
    for (int b = 0; b < BATCH; b++) {
        const float* zb = zs + b * ZDIM;
        float acc = 0.f;
#pragma unroll
        for (int j = 0; j < 16; j++) {
            acc += hwv[j].x * zb[4*j+0];
            acc += hwv[j].y * zb[4*j+1];
            acc += hwv[j].z * zb[4*j+2];
            acc += hwv[j].w * zb[4*j+3];
        }
        float v = c + acc;
        __nv_bfloat16 hi = __float2bfloat16(v);
        size_t o = (size_t)b * (OCN * IC1) + i;     // [b][oc][ic]
        whi[o] = hi;
        wlo[o] = __float2bfloat16(v - __bfloat162float(hi));
    }
}

// ---------------- conv: A staged once per ic-chunk, taps share it --------------------
// Block: 256 thr = 8 warps (4M x 2N). Tile M=128 px (4 oh x 32 ow), N=128 oc.
// A halo region per 64-ic chunk: IH_T x IW_T px, single-buffered (restaged per chunk).
// B per tap: 128oc x 64ic hi/lo, double-buffered via cp.async (overlaps MMA).
// FSC=1: fold 1x1-stride-2 shortcut as a 10th tap (dh=dw=1) into separate accumulator.
template<int IC, int S, int PW, int FSC>
__global__ __launch_bounds__(256) void conv_mma_kernel(
    const __nv_bfloat16* __restrict__ ahi, const __nv_bfloat16* __restrict__ alo,
    const __nv_bfloat16* __restrict__ whi, const __nv_bfloat16* __restrict__ wlo,
    const __nv_bfloat16* __restrict__ wshi, const __nv_bfloat16* __restrict__ wslo,
    float* __restrict__ outp, float* __restrict__ outsc)
{
    constexpr int IW_T = 31 * S + 3;
    constexpr int IH_T = 3 * S + 3;
    constexpr int APX  = IH_T * IW_T;
    constexpr int ABYT = APX * 128;
    constexpr int NT   = 9 + FSC;

    extern __shared__ char smem_raw[];
    uint32_t sb = smem_u32(smem_raw);
    sb = (sb + 1023) & ~1023u;
    const uint32_t S_AH = sb, S_AL = sb + ABYT, S_B = sb + 2 * ABYT;

    const int tx = threadIdx.x, lane = tx & 31, wid = tx >> 5;
    const int warpM = wid & 3, warpN = wid >> 2;
    const int mbase = warpM * 32, nbase = warpN * 64;

    const int b = blockIdx.z, oc0g = blockIdx.y * 128;
    const int oh0 = blockIdx.x * 4, p0 = blockIdx.x * 128;
    const size_t abase = (size_t)b * PW * PW * IC;

    // fragment geometry
    const int colsel = ((lane >> 4) & 1) * 16;
    int ohl[2], owl[2];
#pragma unroll
    for (int mt = 0; mt < 2; mt++) {
        int opx = mbase + mt * 16 + (lane & 15);
        ohl[mt] = opx >> 5; owl[mt] = opx & 31;
    }
    int rB[4];
#pragma unroll
    for (int p = 0; p < 4; p++)
        rB[p] = (nbase + p * 16 + (lane & 7) + ((lane >> 4) & 1) * 8) * 128
              + ((lane >> 3) & 1) * 16;

    float acc[2][8][4] = {};
    float accs[2][8][4] = {};

    auto stageB = [&](int icc, int tap, int buf) {
        uint32_t BH = S_B + (uint32_t)buf * 32768u, BL = BH + 16384u;
        const __nv_bfloat16 *sh, *sl; size_t wb;
        if (FSC && tap == 9) {
            sh = wshi; sl = wslo;
            wb = ((size_t)b * OCN + oc0g) * IC;
        } else {
            sh = whi; sl = wlo;
            wb = (((size_t)b * 9 + tap) * OCN + oc0g) * IC;
        }
#pragma unroll
        for (int pass = 0; pass < 4; pass++) {
            int i = tx + pass * 256;
            int row = i >> 3, chk = i & 7;
            size_t src = wb + (size_t)row * IC + icc * 64 + chk * 8;
            uint32_t so = SWZ(row * 128 + chk * 16);
            CP16(BH + so, (const char*)(sh + src));
            CP16(BL + so, (const char*)(sl + src));
        }
    };

#define MMA_PHASE(ACC)                                                          \
    {                                                                           \
        int arow0 = (ohl[0] * S + dh) * IW_T + owl[0] * S + dw;                 \
        int arow1 = (ohl[1] * S + dh) * IW_T + owl[1] * S + dw;                 \
        _Pragma("unroll")                                                       \
        for (int ks = 0; ks < 4; ks++) {                                        \
            uint32_t ah[2][4], al[2][4], bfr[4][4];                             \
            LDSM4(ah[0], S_AH + SWZ(arow0 * 128 + colsel + ks * 32));           \
            LDSM4(ah[1], S_AH + SWZ(arow1 * 128 + colsel + ks * 32));           \
            LDSM4(al[0], S_AL + SWZ(arow0 * 128 + colsel + ks * 32));           \
            LDSM4(al[1], S_AL + SWZ(arow1 * 128 + colsel + ks * 32));           \
            _Pragma("unroll")                                                   \
            for (int p = 0; p < 4; p++) LDSM4(bfr[p], SBH + SWZ(rB[p] + ks * 32)); \
            _Pragma("unroll")                                                   \
            for (int mt = 0; mt < 2; mt++)                                      \
                _Pragma("unroll")                                               \
                for (int nt = 0; nt < 8; nt++)                                  \
                    MMA16816(ACC[mt][nt], ah[mt], bfr[nt >> 1][(nt & 1) * 2],   \
                             bfr[nt >> 1][(nt & 1) * 2 + 1]);                   \
            _Pragma("unroll")                                                   \
            for (int mt = 0; mt < 2; mt++)                                      \
                _Pragma("unroll")                                               \
                for (int nt = 0; nt < 8; nt++)                                  \
                    MMA16816(ACC[mt][nt], al[mt], bfr[nt >> 1][(nt & 1) * 2],   \
                             bfr[nt >> 1][(nt & 1) * 2 + 1]);                   \
            _Pragma("unroll")                                                   \
            for (int p = 0; p < 4; p++) LDSM4(bfr[p], SBL + SWZ(rB[p] + ks * 32)); \
            _Pragma("unroll")                                                   \
            for (int mt = 0; mt < 2; mt++)                                      \
                _Pragma("unroll")                                               \
                for (int nt = 0; nt < 8; nt++)                                  \
                    MMA16816(ACC[mt][nt], ah[mt], bfr[nt >> 1][(nt & 1) * 2],   \
                             bfr[nt >> 1][(nt & 1) * 2 + 1]);                   \
        }                                                                       \
    }

#pragma unroll 1
    for (int icc = 0; icc < IC / 64; icc++) {
        __syncthreads();   // everyone done reading previous A & B
        // stage A halo region for this ic chunk (all taps share it)
        for (int i = tx; i < APX * 8; i += 256) {
            int row = i >> 3, chk = i & 7;
            int ihl = row / IW_T, iw = row - ihl * IW_T;
            size_t src = abase + ((size_t)(oh0 * S + ihl) * PW + iw) * IC
                       + icc * 64 + chk * 8;
            uint32_t so = SWZ(row * 128 + chk * 16);
            CP16(S_AH + so, (const char*)(ahi + src));
            CP16(S_AL + so, (const char*)(alo + src));
        }
        stageB(icc, 0, 0);
        CPCOMMIT();

#pragma unroll 1
        for (int tap = 0; tap < NT; tap++) {
            CPWAIT0();
            __syncthreads();
            if (tap + 1 < NT) { stageB(icc, tap + 1, (tap + 1) & 1); CPCOMMIT(); }

            const int dh = (FSC && tap == 9) ? 1 : tap / 3;
            const int dw = (FSC && tap == 9) ? 1 : tap % 3;
            const uint32_t SBH = S_B + (uint32_t)(tap & 1) * 32768u, SBL = SBH + 16384u;
            if (FSC && tap == 9) { MMA_PHASE(accs) }
            else                 { MMA_PHASE(acc)  }
        }
    }

    // ---- epilogue: NHWC fp32 ----
    float* ob = outp + (size_t)b * NPIX * OCN + oc0g;
#pragma unroll
    for (int mt = 0; mt < 2; mt++) {
        int px0 = p0 + mbase + mt * 16 + (lane >> 2);
#pragma unroll
        for (int nt = 0; nt < 8; nt++) {
            int oc = nbase + nt * 8 + (lane & 3) * 2;
            *(float2*)(ob + (size_t)px0 * OCN + oc) =
                make_float2(acc[mt][nt][0], acc[mt][nt][1]);
            *(float2*)(ob + (size_t)(px0 + 8) * OCN + oc) =
                make_float2(acc[mt][nt][2], acc[mt][nt][3]);
        }
    }
    if (FSC) {
        float* os = outsc + (size_t)b * NPIX * OCN + oc0g;
#pragma unroll
        for (int mt = 0; mt < 2; mt++) {
            int px0 = p0 + mbase + mt * 16 + (lane >> 2);
#pragma unroll
            for (int nt = 0; nt < 8; nt++) {
                int oc = nbase + nt * 8 + (lane & 3) * 2;
                *(float2*)(os + (size_t)px0 * OCN + oc) =
                    make_float2(accs[mt][nt][0], accs[mt][nt][1]);
                *(float2*)(os + (size_t)(px0 + 8) * OCN + oc) =
                    make_float2(accs[mt][nt][2], accs[mt][nt][3]);
            }
        }
    }
#undef MMA_PHASE
}

#define CONV1_SMEM (1024 + 2 * (585 * 128) + 4 * 16384)   // 216320
#define CONV2_SMEM (1024 + 2 * (204 * 128) + 4 * 16384)   // 118784

// ---------------- GroupNorm stats on NHWC fp32 ----------------
__global__ __launch_bounds__(256) void gn_stats_kernel(
    const float* __restrict__ x, float* __restrict__ stats)
{
    const int bg = blockIdx.x;
    const int b = bg >> 3, g = bg & 7;
    const float* base = x + (size_t)b * NPIX * OCN + g * 32;
    float s = 0.f, ss = 0.f;
    for (int i = threadIdx.x; i < NPIX * 8; i += 256) {
        int px = i >> 3, c4 = i & 7;
        float4 v = *(const float4*)(base + (size_t)px * OCN + c4 * 4);
        s += v.x + v.y + v.z + v.w;
        ss += v.x * v.x + v.y * v.y + v.z * v.z + v.w * v.w;
    }
    __shared__ float sh0[256], sh1[256];
    sh0[threadIdx.x] = s; sh1[threadIdx.x] = ss;
    __syncthreads();
    for (int o = 128; o > 0; o >>= 1) {
        if (threadIdx.x < o) { sh0[threadIdx.x] += sh0[threadIdx.x + o]; sh1[threadIdx.x] += sh1[threadIdx.x + o]; }
        __syncthreads();
    }
    if (threadIdx.x == 0) {
        const float n = 32768.f;
        float mu = sh0[0] / n;
        float var = sh1[0] / n - mu * mu;
        stats[bg * 2 + 0] = mu;
        stats[bg * 2 + 1] = rsqrtf(var + EPSV);
    }
}

// ---------------- GN1 + ReLU -> padded NHWC bf16 hi/lo (vectorized) ----------------
__global__ __launch_bounds__(256) void gn1_prep_kernel(
    const float* __restrict__ x, const float* __restrict__ stats,
    const float* __restrict__ gamma, const float* __restrict__ beta,
    __nv_bfloat16* __restrict__ ahi, __nv_bfloat16* __restrict__ alo)
{
    const size_t t = (size_t)blockIdx.x * 256 + threadIdx.x;   // over 16*1024*64
    const int c = (int)(t & 63) * 4;
    const int px = (int)((t >> 6) & 1023);
    const int b = (int)(t >> 16);
    const int bg = b * NGRP + (c >> 5);
    const float mu = stats[bg * 2], ri = stats[bg * 2 + 1];
    float4 xv = *(const float4*)(x + ((size_t)b * NPIX + px) * OCN + c);
    float4 g4 = *(const float4*)(gamma + c);
    float4 b4 = *(const float4*)(beta + c);
    float v[4] = {(xv.x - mu) * ri * g4.x + b4.x, (xv.y - mu) * ri * g4.y + b4.y,
                  (xv.z - mu) * ri * g4.z + b4.z, (xv.w - mu) * ri * g4.w + b4.w};
    __nv_bfloat16 hi[4], lo[4];
#pragma unroll
    for (int j = 0; j < 4; j++) {
        float vv = fmaxf(v[j], 0.f);
        hi[j] = __float2bfloat16(vv);
        lo[j] = __float2bfloat16(vv - __bfloat162float(hi[j]));
    }
    const int oh = px >> 5, ow = px & 31;
    size_t o = (((size_t)b * PW2 + oh + 1) * PW2 + ow + 1) * OCN + c;
    *(uint2*)(ahi + o) = make_uint2(pk_bf2(hi[0], hi[1]), pk_bf2(hi[2], hi[3]));
    *(uint2*)(alo + o) = make_uint2(pk_bf2(lo[0], lo[1]), pk_bf2(lo[2], lo[3]));
}

// ---------------- final: relu(GN2(conv2) + shortcut), NHWC -> NCHW ----------------
__global__ __launch_bounds__(256) void final_kernel(
    const float* __restrict__ x, const float* __restrict__ sc,
    const float* __restrict__ stats,
    const float* __restrict__ gamma, const float* __restrict__ beta,
    float* __restrict__ out)
{
    __shared__ float s[32][33];
    const int pt = blockIdx.x, ct = blockIdx.y, b = blockIdx.z;
    const int px0 = pt * 32, c0 = ct * 32;
    const int tx = threadIdx.x;
    const int bg = b * NGRP + (c0 >> 5);
    const float mu = stats[bg * 2], ri = stats[bg * 2 + 1];
#pragma unroll
    for (int k = 0; k < 4; k++) {
        int idx = tx + k * 256;
        int pi = idx >> 5, ci = idx & 31;
        size_t o = ((size_t)b * NPIX + px0 + pi) * OCN + c0 + ci;
        float v = (x[o] - mu) * ri * gamma[c0 + ci] + beta[c0 + ci] + sc[o];
        s[pi][ci] = fmaxf(v, 0.f);
    }
    __syncthreads();
#pragma unroll
    for (int k = 0; k < 4; k++) {
        int idx = tx + k * 256;
        int cj = idx >> 5, wi = idx & 31;
        out[((size_t)b * OCN + c0 + cj) * NPIX + px0 + wi] = s[wi][cj];
    }
}

// ---------------- launch ----------------
extern "C" void kernel_launch(void* const* d_in, const int* in_sizes, int n_in,
                              void* d_out, int out_size)
{
    const float* x        = (const float*)d_in[0];
    const float* z        = (const float*)d_in[1];
    const float* base_w1  = (const float*)d_in[2];
    const float* head_w1  = (const float*)d_in[3];
    const float* head_b1  = (const float*)d_in[4];
    const float* gn_w1    = (const float*)d_in[5];
    const float* gn_b1    = (const float*)d_in[6];
    const float* base_w2  = (const float*)d_in[7];
    const float* head_w2  = (const float*)d_in[8];
    const float* head_b2  = (const float*)d_in[9];
    const float* gn_w2    = (const float*)d_in[10];
    const float* gn_b2    = (const float*)d_in[11];
    const float* base_wsc = (const float*)d_in[12];
    const float* head_wsc = (const float*)d_in[13];
    const float* head_bsc = (const float*)d_in[14];
    float* out = (float*)d_out;

    __nv_bfloat16 *xhi, *xlo, *ahi, *alo, *w1hi, *w1lo, *w2hi, *w2lo, *wshi, *wslo;
    float *c1p, *c2p, *scp, *st1, *st2;
    cudaGetSymbolAddress((void**)&xhi,  g_xhi);  cudaGetSymbolAddress((void**)&xlo,  g_xlo);
    cudaGetSymbolAddress((void**)&ahi,  g_ahi);  cudaGetSymbolAddress((void**)&alo,  g_alo);
    cudaGetSymbolAddress((void**)&w1hi, g_w1hi); cudaGetSymbolAddress((void**)&w1lo, g_w1lo);
    cudaGetSymbolAddress((void**)&w2hi, g_w2hi); cudaGetSymbolAddress((void**)&w2lo, g_w2lo);
    cudaGetSymbolAddress((void**)&wshi, g_wshi); cudaGetSymbolAddress((void**)&wslo, g_wslo);
    cudaGetSymbolAddress((void**)&c1p,  g_c1out); cudaGetSymbolAddress((void**)&c2p, g_c2out);
    cudaGetSymbolAddress((void**)&scp,  g_scout);
    cudaGetSymbolAddress((void**)&st1,  g_st1);  cudaGetSymbolAddress((void**)&st2,  g_st2);

    cudaFuncSetAttribute(conv_mma_kernel<IC1, 2, PW1, 1>, cudaFuncAttributeMaxDynamicSharedMemorySize, CONV1_SMEM);
    cudaFuncSetAttribute(conv_mma_kernel<OCN, 1, PW2, 0>, cudaFuncAttributeMaxDynamicSharedMemorySize, CONV2_SMEM);

    // 1. prep x -> padded NHWC bf16 hi/lo
    prep_x_kernel<<<dim3(8, 64, 16), 256>>>(x, xhi, xlo);

    // 2. modulated weights (bf16 hi/lo)
    modw_kernel<9, IC1><<<OCN * (IC1 / 8), 288>>>(base_w1,  head_w1,  head_b1,  z, w1hi, w1lo);
    modw_kernel<9, OCN><<<OCN * (OCN / 8), 288>>>(base_w2,  head_w2,  head_b2,  z, w2hi, w2lo);
    modw1_kernel<<<(OCN * IC1) / 256, 256>>>(base_wsc, head_wsc, head_bsc, z, wshi, wslo);

    // 3. conv1 (3x3 s2) with fused 1x1-s2 shortcut
    conv_mma_kernel<IC1, 2, PW1, 1><<<dim3(8, 2, 16), 256, CONV1_SMEM>>>(
        xhi, xlo, w1hi, w1lo, wshi, wslo, c1p, scp);

    // 4. GN1 + ReLU -> padded NHWC bf16 hi/lo
    gn_stats_kernel<<<BATCH * NGRP, 256>>>(c1p, st1);
    gn1_prep_kernel<<<(BATCH * NPIX * OCN / 4) / 256, 256>>>(c1p, st1, gn_w1, gn_b1, ahi, alo);

    // 5. conv2 (3x3 s1)
    conv_mma_kernel<OCN, 1, PW2, 0><<<dim3(8, 2, 16), 256, CONV2_SMEM>>>(
        ahi, alo, w2hi, w2lo, (const __nv_bfloat16*)nullptr, (const __nv_bfloat16*)nullptr,
        c2p, (float*)nullptr);

    // 6. GN2 + residual + ReLU -> NCHW out
    gn_stats_kernel<<<BATCH * NGRP, 256>>>(c2p, st2);
    final_kernel<<<dim3(32, 8, 16), 256>>>(c2p, scp, st2, gn_w2, gn_b2, out);
}

// round 7
// speedup vs baseline: 4.0885x; 1.4603x over previous
#include <cuda_runtime.h>
#include <cuda_fp16.h>
#include <cstdint>

// ---------------- problem dims ----------------
#define BATCH 16
#define IC1   128
#define OCN   256
#define ZDIM  64
#define HIN   64
#define WIN   64
#define HO    32
#define WO    32
#define NPIX  1024
#define NGRP  8
#define EPSV  1e-5f
#define PW1   66     // padded x: 66x66
#define PW2   34     // padded act1: 34x34

// ---------------- scratch (__device__ globals zero-init; halos stay 0) ----------------
__device__ __half g_xh [(size_t)BATCH*PW1*PW1*IC1];
__device__ __half g_ah [(size_t)BATCH*PW2*PW2*OCN];
__device__ __half g_w1 [(size_t)BATCH*9*OCN*IC1];
__device__ __half g_w2 [(size_t)BATCH*9*OCN*OCN];
__device__ __half g_ws [(size_t)BATCH*OCN*IC1];
__device__ float g_c1out[(size_t)BATCH*NPIX*OCN];   // NHWC fp32
__device__ float g_c2out[(size_t)BATCH*NPIX*OCN];
__device__ float g_scout[(size_t)BATCH*NPIX*OCN];
__device__ float g_st1[BATCH*NGRP*2];
__device__ float g_st2[BATCH*NGRP*2];

// ---------------- helpers ----------------
__device__ __forceinline__ uint32_t smem_u32(const void* p) {
    uint32_t a;
    asm("{ .reg .u64 t; cvta.to.shared.u64 t, %1; cvt.u32.u64 %0, t; }" : "=r"(a) : "l"(p));
    return a;
}
#define SWZ(x) ((uint32_t)(x) ^ ((((uint32_t)(x)) >> 3) & 0x70u))

#define CP16(dst, src) \
    asm volatile("cp.async.cg.shared.global [%0], [%1], 16;" :: "r"(dst), "l"(src))
#define CPCOMMIT() asm volatile("cp.async.commit_group;" ::: "memory")
#define CPWAIT0()  asm volatile("cp.async.wait_group 0;" ::: "memory")

#define LDSM4(r, addr) \
    asm volatile("ldmatrix.sync.aligned.m8n8.x4.shared.b16 {%0,%1,%2,%3}, [%4];" \
                 : "=r"((r)[0]), "=r"((r)[1]), "=r"((r)[2]), "=r"((r)[3]) : "r"(addr))

#define MMA16816(c, a, b0, b1) \
    asm volatile("mma.sync.aligned.m16n8k16.row.col.f32.f16.f16.f32 " \
                 "{%0,%1,%2,%3}, {%4,%5,%6,%7}, {%8,%9}, {%0,%1,%2,%3};" \
                 : "+f"((c)[0]), "+f"((c)[1]), "+f"((c)[2]), "+f"((c)[3]) \
                 : "r"((a)[0]), "r"((a)[1]), "r"((a)[2]), "r"((a)[3]), "r"(b0), "r"(b1))

__device__ __forceinline__ uint32_t pk_h2(float a, float b) {
    __half2 t = __floats2half2_rn(a, b);
    return *(uint32_t*)&t;
}

// ---------------- prep: x NCHW fp32 -> padded NHWC fp16 ----------------
__global__ __launch_bounds__(256) void prep_x_kernel(
    const float* __restrict__ x, __half* __restrict__ xh)
{
    __shared__ float s[32][33];
    const int wt = blockIdx.x & 1, ct = blockIdx.x >> 1;
    const int h = blockIdx.y, b = blockIdx.z;
    const int w0 = wt * 32, c0 = ct * 32;
    const int tx = threadIdx.x;
#pragma unroll
    for (int k = 0; k < 4; k++) {
        int idx = tx + k * 256;
        int ci = idx >> 5, wi = idx & 31;
        s[wi][ci] = x[(((size_t)b * IC1 + c0 + ci) * HIN + h) * WIN + w0 + wi];
    }
    __syncthreads();
    const int wi = tx >> 3, cg = tx & 7;   // 4 consecutive channels -> 8B store
    size_t o = (((size_t)b * PW1 + h + 1) * PW1 + (w0 + wi + 1)) * IC1 + c0 + cg * 4;
    *(uint2*)(xh + o) = make_uint2(pk_h2(s[wi][cg*4+0], s[wi][cg*4+1]),
                                   pk_h2(s[wi][cg*4+2], s[wi][cg*4+3]));
}

// ---------------- weight modulation (3x3): fp16, [b][tap][oc][ic] ----------------
template<int NTAP, int IC>
__global__ void modw_kernel(
    const float* __restrict__ base, const float* __restrict__ hw,
    const float* __restrict__ hb,   const float* __restrict__ z,
    __half* __restrict__ wout)
{
    constexpr int ROWS = 8 * NTAP;
    constexpr int BT   = 32 * NTAP;
    __shared__ float hwS[ROWS * 65];
    __shared__ float zs[BATCH * ZDIM];
    __shared__ float cb[ROWS];
    const int oc  = blockIdx.x / (IC / 8);
    const int ic0 = (blockIdx.x % (IC / 8)) * 8;
    const int gi0 = (oc * IC + ic0) * NTAP;
    const int tx = threadIdx.x;
    for (int i = tx; i < ROWS * 64; i += BT)
        hwS[(i >> 6) * 65 + (i & 63)] = hw[(size_t)gi0 * 64 + i];
    for (int i = tx; i < BATCH * ZDIM; i += BT) zs[i] = z[i];
    for (int i = tx; i < ROWS; i += BT) cb[i] = base[gi0 + i] + hb[gi0 + i];
    __syncthreads();

    const int icl = tx & 7;
    const int tap = (tx >> 3) % NTAP;
    const int bq  = tx / (8 * NTAP);
    const int r   = icl * NTAP + tap;
    float acc[4] = {0.f, 0.f, 0.f, 0.f};
    for (int j = 0; j < 64; j++) {
        float h = hwS[r * 65 + j];
        acc[0] += h * zs[(bq * 4 + 0) * 64 + j];
        acc[1] += h * zs[(bq * 4 + 1) * 64 + j];
        acc[2] += h * zs[(bq * 4 + 2) * 64 + j];
        acc[3] += h * zs[(bq * 4 + 3) * 64 + j];
    }
#pragma unroll
    for (int bb = 0; bb < 4; bb++) {
        int b = bq * 4 + bb;
        size_t o = (((size_t)b * NTAP + tap) * OCN + oc) * IC + ic0 + icl;
        wout[o] = __float2half_rn(cb[r] + acc[bb]);
    }
}

// ---------------- weight modulation (1x1 shortcut): one thread per row ----------------
__global__ __launch_bounds__(256) void modw1_kernel(
    const float* __restrict__ base, const float* __restrict__ hw,
    const float* __restrict__ hb,   const float* __restrict__ z,
    __half* __restrict__ wout)
{
    __shared__ float zs[BATCH * ZDIM];
    for (int i = threadIdx.x; i < BATCH * ZDIM; i += 256) zs[i] = z[i];
    __syncthreads();

    const int i = blockIdx.x * 256 + threadIdx.x;
    float4 hwv[16];
    const float4* hwp = (const float4*)(hw + (size_t)i * ZDIM);
#pragma unroll
    for (int j = 0; j < 16; j++) hwv[j] = hwp[j];
    const float c = base[i] + hb[i];
#pragma unroll
    for (int b = 0; b < BATCH; b++) {
        const float* zb = zs + b * ZDIM;
        float acc = 0.f;
#pragma unroll
        for (int j = 0; j < 16; j++) {
            acc += hwv[j].x * zb[4*j+0];
            acc += hwv[j].y * zb[4*j+1];
            acc += hwv[j].z * zb[4*j+2];
            acc += hwv[j].w * zb[4*j+3];
        }
        wout[(size_t)b * (OCN * IC1) + i] = __float2half_rn(c + acc);
    }
}

// ---------------- conv: fp16 1-pass, A staged once per ic-chunk, taps share it ------
// Block: 256 thr = 8 warps (4M x 2N). Tile M=128 px (4 oh x 32 ow), N=128 oc.
// A halo region per 64-ic chunk (single buffer); B per tap double-buffered (cp.async).
// FSC=1: fold 1x1-s2 shortcut as 10th tap (dh=dw=1) into separate accumulator.
template<int IC, int S, int PW, int FSC>
__global__ __launch_bounds__(256) void conv_mma_kernel(
    const __half* __restrict__ ain,
    const __half* __restrict__ win,
    const __half* __restrict__ wsin,
    float* __restrict__ outp, float* __restrict__ outsc)
{
    constexpr int IW_T = 31 * S + 3;
    constexpr int IH_T = 3 * S + 3;
    constexpr int APX  = IH_T * IW_T;
    constexpr int ABYT = APX * 128;          // 64 fp16 per row = 128B
    constexpr int NT   = 9 + FSC;

    extern __shared__ char smem_raw[];
    uint32_t sb = smem_u32(smem_raw);
    sb = (sb + 1023) & ~1023u;
    const uint32_t S_A = sb, S_B = sb + ABYT;

    const int tx = threadIdx.x, lane = tx & 31, wid = tx >> 5;
    const int warpM = wid & 3, warpN = wid >> 2;
    const int mbase = warpM * 32, nbase = warpN * 64;

    const int b = blockIdx.z, oc0g = blockIdx.y * 128;
    const int oh0 = blockIdx.x * 4, p0 = blockIdx.x * 128;
    const size_t abase = (size_t)b * PW * PW * IC;

    const int colsel = ((lane >> 4) & 1) * 16;
    int ohl[2], owl[2];
#pragma unroll
    for (int mt = 0; mt < 2; mt++) {
        int opx = mbase + mt * 16 + (lane & 15);
        ohl[mt] = opx >> 5; owl[mt] = opx & 31;
    }
    int rB[4];
#pragma unroll
    for (int p = 0; p < 4; p++)
        rB[p] = (nbase + p * 16 + (lane & 7) + ((lane >> 4) & 1) * 8) * 128
              + ((lane >> 3) & 1) * 16;

    float acc[2][8][4] = {};
    float accs[2][8][4] = {};

    auto stageB = [&](int icc, int tap, int buf) {
        uint32_t BH = S_B + (uint32_t)buf * 16384u;
        const __half* sh; size_t wb;
        if (FSC && tap == 9) {
            sh = wsin;
            wb = ((size_t)b * OCN + oc0g) * IC;
        } else {
            sh = win;
            wb = (((size_t)b * 9 + tap) * OCN + oc0g) * IC;
        }
#pragma unroll
        for (int pass = 0; pass < 4; pass++) {
            int i = tx + pass * 256;
            int row = i >> 3, chk = i & 7;
            size_t src = wb + (size_t)row * IC + icc * 64 + chk * 8;
            CP16(BH + SWZ(row * 128 + chk * 16), (const char*)(sh + src));
        }
    };

#define MMA_PHASE(ACC)                                                          \
    {                                                                           \
        int arow0 = (ohl[0] * S + dh) * IW_T + owl[0] * S + dw;                 \
        int arow1 = (ohl[1] * S + dh) * IW_T + owl[1] * S + dw;                 \
        _Pragma("unroll")                                                       \
        for (int ks = 0; ks < 4; ks++) {                                        \
            uint32_t ah[2][4], bfr[4][4];                                       \
            LDSM4(ah[0], S_A + SWZ(arow0 * 128 + colsel + ks * 32));            \
            LDSM4(ah[1], S_A + SWZ(arow1 * 128 + colsel + ks * 32));            \
            _Pragma("unroll")                                                   \
            for (int p = 0; p < 4; p++) LDSM4(bfr[p], SB + SWZ(rB[p] + ks * 32)); \
            _Pragma("unroll")                                                   \
            for (int mt = 0; mt < 2; mt++)                                      \
                _Pragma("unroll")                                               \
                for (int nt = 0; nt < 8; nt++)                                  \
                    MMA16816(ACC[mt][nt], ah[mt], bfr[nt >> 1][(nt & 1) * 2],   \
                             bfr[nt >> 1][(nt & 1) * 2 + 1]);                   \
        }                                                                       \
    }

#pragma unroll 1
    for (int icc = 0; icc < IC / 64; icc++) {
        __syncthreads();   // all warps done reading previous A & B
        // stage A halo region (all taps share it)
        for (int i = tx; i < APX * 8; i += 256) {
            int row = i >> 3, chk = i & 7;
            int ihl = row / IW_T, iw = row - ihl * IW_T;
            size_t src = abase + ((size_t)(oh0 * S + ihl) * PW + iw) * IC
                       + icc * 64 + chk * 8;
            CP16(S_A + SWZ(row * 128 + chk * 16), (const char*)(ain + src));
        }
        stageB(icc, 0, 0);
        CPCOMMIT();

#pragma unroll 1
        for (int tap = 0; tap < NT; tap++) {
            CPWAIT0();
            __syncthreads();
            if (tap + 1 < NT) { stageB(icc, tap + 1, (tap + 1) & 1); CPCOMMIT(); }

            const int dh = (FSC && tap == 9) ? 1 : tap / 3;
            const int dw = (FSC && tap == 9) ? 1 : tap % 3;
            const uint32_t SB = S_B + (uint32_t)(tap & 1) * 16384u;
            if (FSC && tap == 9) { MMA_PHASE(accs) }
            else                 { MMA_PHASE(acc)  }
        }
    }

    // ---- epilogue: NHWC fp32 ----
    float* ob = outp + (size_t)b * NPIX * OCN + oc0g;
#pragma unroll
    for (int mt = 0; mt < 2; mt++) {
        int px0 = p0 + mbase + mt * 16 + (lane >> 2);
#pragma unroll
        for (int nt = 0; nt < 8; nt++) {
            int oc = nbase + nt * 8 + (lane & 3) * 2;
            *(float2*)(ob + (size_t)px0 * OCN + oc) =
                make_float2(acc[mt][nt][0], acc[mt][nt][1]);
            *(float2*)(ob + (size_t)(px0 + 8) * OCN + oc) =
                make_float2(acc[mt][nt][2], acc[mt][nt][3]);
        }
    }
    if (FSC) {
        float* os = outsc + (size_t)b * NPIX * OCN + oc0g;
#pragma unroll
        for (int mt = 0; mt < 2; mt++) {
            int px0 = p0 + mbase + mt * 16 + (lane >> 2);
#pragma unroll
            for (int nt = 0; nt < 8; nt++) {
                int oc = nbase + nt * 8 + (lane & 3) * 2;
                *(float2*)(os + (size_t)px0 * OCN + oc) =
                    make_float2(accs[mt][nt][0], accs[mt][nt][1]);
                *(float2*)(os + (size_t)(px0 + 8) * OCN + oc) =
                    make_float2(accs[mt][nt][2], accs[mt][nt][3]);
            }
        }
    }
#undef MMA_PHASE
}

#define CONV1_SMEM (1024 + 585 * 128 + 2 * 16384)   // 108672
#define CONV2_SMEM (1024 + 204 * 128 + 2 * 16384)   // 59904

// ---------------- GroupNorm stats on NHWC fp32 ----------------
__global__ __launch_bounds__(256) void gn_stats_kernel(
    const float* __restrict__ x, float* __restrict__ stats)
{
    const int bg = blockIdx.x;
    const int b = bg >> 3, g = bg & 7;
    const float* base = x + (size_t)b * NPIX * OCN + g * 32;
    float s = 0.f, ss = 0.f;
    for (int i = threadIdx.x; i < NPIX * 8; i += 256) {
        int px = i >> 3, c4 = i & 7;
        float4 v = *(const float4*)(base + (size_t)px * OCN + c4 * 4);
        s += v.x + v.y + v.z + v.w;
        ss += v.x * v.x + v.y * v.y + v.z * v.z + v.w * v.w;
    }
    __shared__ float sh0[256], sh1[256];
    sh0[threadIdx.x] = s; sh1[threadIdx.x] = ss;
    __syncthreads();
    for (int o = 128; o > 0; o >>= 1) {
        if (threadIdx.x < o) { sh0[threadIdx.x] += sh0[threadIdx.x + o]; sh1[threadIdx.x] += sh1[threadIdx.x + o]; }
        __syncthreads();
    }
    if (threadIdx.x == 0) {
        const float n = 32768.f;
        float mu = sh0[0] / n;
        float var = sh1[0] / n - mu * mu;
        stats[bg * 2 + 0] = mu;
        stats[bg * 2 + 1] = rsqrtf(var + EPSV);
    }
}

// ---------------- GN1 + ReLU -> padded NHWC fp16 ----------------
__global__ __launch_bounds__(256) void gn1_prep_kernel(
    const float* __restrict__ x, const float* __restrict__ stats,
    const float* __restrict__ gamma, const float* __restrict__ beta,
    __half* __restrict__ ah)
{
    const size_t t = (size_t)blockIdx.x * 256 + threadIdx.x;   // 16*1024*64
    const int c = (int)(t & 63) * 4;
    const int px = (int)((t >> 6) & 1023);
    const int b = (int)(t >> 16);
    const int bg = b * NGRP + (c >> 5);
    const float mu = stats[bg * 2], ri = stats[bg * 2 + 1];
    float4 xv = *(const float4*)(x + ((size_t)b * NPIX + px) * OCN + c);
    float4 g4 = *(const float4*)(gamma + c);
    float4 b4 = *(const float4*)(beta + c);
    float v0 = fmaxf((xv.x - mu) * ri * g4.x + b4.x, 0.f);
    float v1 = fmaxf((xv.y - mu) * ri * g4.y + b4.y, 0.f);
    float v2 = fmaxf((xv.z - mu) * ri * g4.z + b4.z, 0.f);
    float v3 = fmaxf((xv.w - mu) * ri * g4.w + b4.w, 0.f);
    const int oh = px >> 5, ow = px & 31;
    size_t o = (((size_t)b * PW2 + oh + 1) * PW2 + ow + 1) * OCN + c;
    *(uint2*)(ah + o) = make_uint2(pk_h2(v0, v1), pk_h2(v2, v3));
}

// ---------------- final: relu(GN2(conv2) + shortcut), NHWC -> NCHW ----------------
__global__ __launch_bounds__(256) void final_kernel(
    const float* __restrict__ x, const float* __restrict__ sc,
    const float* __restrict__ stats,
    const float* __restrict__ gamma, const float* __restrict__ beta,
    float* __restrict__ out)
{
    __shared__ float s[32][33];
    const int pt = blockIdx.x, ct = blockIdx.y, b = blockIdx.z;
    const int px0 = pt * 32, c0 = ct * 32;
    const int tx = threadIdx.x;
    const int bg = b * NGRP + (c0 >> 5);
    const float mu = stats[bg * 2], ri = stats[bg * 2 + 1];
#pragma unroll
    for (int k = 0; k < 4; k++) {
        int idx = tx + k * 256;
        int pi = idx >> 5, ci = idx & 31;
        size_t o = ((size_t)b * NPIX + px0 + pi) * OCN + c0 + ci;
        float v = (x[o] - mu) * ri * gamma[c0 + ci] + beta[c0 + ci] + sc[o];
        s[pi][ci] = fmaxf(v, 0.f);
    }
    __syncthreads();
#pragma unroll
    for (int k = 0; k < 4; k++) {
        int idx = tx + k * 256;
        int cj = idx >> 5, wi = idx & 31;
        out[((size_t)b * OCN + c0 + cj) * NPIX + px0 + wi] = s[wi][cj];
    }
}

// ---------------- launch ----------------
extern "C" void kernel_launch(void* const* d_in, const int* in_sizes, int n_in,
                              void* d_out, int out_size)
{
    const float* x        = (const float*)d_in[0];
    const float* z        = (const float*)d_in[1];
    const float* base_w1  = (const float*)d_in[2];
    const float* head_w1  = (const float*)d_in[3];
    const float* head_b1  = (const float*)d_in[4];
    const float* gn_w1    = (const float*)d_in[5];
    const float* gn_b1    = (const float*)d_in[6];
    const float* base_w2  = (const float*)d_in[7];
    const float* head_w2  = (const float*)d_in[8];
    const float* head_b2  = (const float*)d_in[9];
    const float* gn_w2    = (const float*)d_in[10];
    const float* gn_b2    = (const float*)d_in[11];
    const float* base_wsc = (const float*)d_in[12];
    const float* head_wsc = (const float*)d_in[13];
    const float* head_bsc = (const float*)d_in[14];
    float* out = (float*)d_out;

    __half *xh, *ah, *w1, *w2, *ws;
    float *c1p, *c2p, *scp, *st1, *st2;
    cudaGetSymbolAddress((void**)&xh, g_xh);
    cudaGetSymbolAddress((void**)&ah, g_ah);
    cudaGetSymbolAddress((void**)&w1, g_w1);
    cudaGetSymbolAddress((void**)&w2, g_w2);
    cudaGetSymbolAddress((void**)&ws, g_ws);
    cudaGetSymbolAddress((void**)&c1p, g_c1out);
    cudaGetSymbolAddress((void**)&c2p, g_c2out);
    cudaGetSymbolAddress((void**)&scp, g_scout);
    cudaGetSymbolAddress((void**)&st1, g_st1);
    cudaGetSymbolAddress((void**)&st2, g_st2);

    cudaFuncSetAttribute(conv_mma_kernel<IC1, 2, PW1, 1>, cudaFuncAttributeMaxDynamicSharedMemorySize, CONV1_SMEM);
    cudaFuncSetAttribute(conv_mma_kernel<OCN, 1, PW2, 0>, cudaFuncAttributeMaxDynamicSharedMemorySize, CONV2_SMEM);

    // 1. prep x -> padded NHWC fp16
    prep_x_kernel<<<dim3(8, 64, 16), 256>>>(x, xh);

    // 2. modulated weights (fp16)
    modw_kernel<9, IC1><<<OCN * (IC1 / 8), 288>>>(base_w1, head_w1, head_b1, z, w1);
    modw_kernel<9, OCN><<<OCN * (OCN / 8), 288>>>(base_w2, head_w2, head_b2, z, w2);
    modw1_kernel<<<(OCN * IC1) / 256, 256>>>(base_wsc, head_wsc, head_bsc, z, ws);

    // 3. conv1 (3x3 s2) with fused 1x1-s2 shortcut
    conv_mma_kernel<IC1, 2, PW1, 1><<<dim3(8, 2, 16), 256, CONV1_SMEM>>>(
        xh, w1, ws, c1p, scp);

    // 4. GN1 + ReLU -> padded NHWC fp16
    gn_stats_kernel<<<BATCH * NGRP, 256>>>(c1p, st1);
    gn1_prep_kernel<<<(BATCH * NPIX * OCN / 4) / 256, 256>>>(c1p, st1, gn_w1, gn_b1, ah);

    // 5. conv2 (3x3 s1)
    conv_mma_kernel<OCN, 1, PW2, 0><<<dim3(8, 2, 16), 256, CONV2_SMEM>>>(
        ah, w2, (const __half*)nullptr, c2p, (float*)nullptr);

    // 6. GN2 + residual + ReLU -> NCHW out
    gn_stats_kernel<<<BATCH * NGRP, 256>>>(c2p, st2);
    final_kernel<<<dim3(32, 8, 16), 256>>>(c2p, scp, st2, gn_w2, gn_b2, out);
}